// round 4
// baseline (speedup 1.0000x reference)
#include <cuda_runtime.h>
#include <math.h>

// Problem constants
#define Bb  4
#define Aa  3
#define Ss  1024
#define Hh  768
#define NHh 12
#define HDd 64

// Device scratch (allocation-free rule: __device__ globals)
__device__ float g_Q  [Bb*Ss*Hh];          // Q projection  [B,S,NH,HD]
__device__ float g_K  [Bb*Aa*Ss*Hh];       // K projection  [B,A,S,NH,HD]
__device__ float g_V  [Bb*Aa*Ss*Hh];       // V projection  [B,A,S,NH,HD]
__device__ float g_att[Bb*Ss*Hh];          // attended      [B,S,NH,HD]
__device__ float g_O  [Bb*Ss*Hh];          // pre-LN (proj + residual)

// ---------------------------------------------------------------------------
// GEMM: out[m,n] = sum_k X[m,k]*W[n,k] + bias[n] (+ res[m,n] if ADD)
// BM=BN=128, BK=16, 256 threads, 8x8 register tile per thread.
// ---------------------------------------------------------------------------
template<bool ADD>
__global__ __launch_bounds__(256)
void gemm_bias(const float* __restrict__ X, const float* __restrict__ W,
               const float* __restrict__ bias, const float* __restrict__ res,
               float* __restrict__ out, int M, int N, int K)
{
    const int BM = 128, BN = 128, BK = 16;
    __shared__ float Xs[BK][BM + 4];
    __shared__ float Ws[BK][BN + 4];

    const int m0 = blockIdx.y * BM;
    const int n0 = blockIdx.x * BN;
    const int tid = threadIdx.x;
    const int tx = tid & 15;
    const int ty = tid >> 4;

    float acc[8][8];
#pragma unroll
    for (int i = 0; i < 8; i++)
#pragma unroll
        for (int j = 0; j < 8; j++) acc[i][j] = 0.f;

    for (int k0 = 0; k0 < K; k0 += BK) {
#pragma unroll
        for (int p = 0; p < 2; p++) {
            int r = (tid >> 2) + p * 64;
            int c = (tid & 3) * 4;
            float4 xv = *(const float4*)(X + (size_t)(m0 + r) * K + k0 + c);
            Xs[c + 0][r] = xv.x; Xs[c + 1][r] = xv.y;
            Xs[c + 2][r] = xv.z; Xs[c + 3][r] = xv.w;
            float4 wv = *(const float4*)(W + (size_t)(n0 + r) * K + k0 + c);
            Ws[c + 0][r] = wv.x; Ws[c + 1][r] = wv.y;
            Ws[c + 2][r] = wv.z; Ws[c + 3][r] = wv.w;
        }
        __syncthreads();

#pragma unroll
        for (int k = 0; k < BK; k++) {
            float4 a0 = *(float4*)&Xs[k][ty * 8];
            float4 a1 = *(float4*)&Xs[k][ty * 8 + 4];
            float4 b0 = *(float4*)&Ws[k][tx * 8];
            float4 b1 = *(float4*)&Ws[k][tx * 8 + 4];
            float a[8] = {a0.x, a0.y, a0.z, a0.w, a1.x, a1.y, a1.z, a1.w};
            float bb[8] = {b0.x, b0.y, b0.z, b0.w, b1.x, b1.y, b1.z, b1.w};
#pragma unroll
            for (int i = 0; i < 8; i++)
#pragma unroll
                for (int j = 0; j < 8; j++)
                    acc[i][j] += a[i] * bb[j];
        }
        __syncthreads();
    }

#pragma unroll
    for (int i = 0; i < 8; i++) {
        int m = m0 + ty * 8 + i;
#pragma unroll
        for (int j = 0; j < 8; j += 4) {
            int n = n0 + tx * 8 + j;
            float4 o;
            o.x = acc[i][j + 0] + bias[n + 0];
            o.y = acc[i][j + 1] + bias[n + 1];
            o.z = acc[i][j + 2] + bias[n + 2];
            o.w = acc[i][j + 3] + bias[n + 3];
            if (ADD) {
                float4 rr = *(const float4*)(res + (size_t)m * N + n);
                o.x += rr.x; o.y += rr.y; o.z += rr.z; o.w += rr.w;
            }
            *(float4*)(out + (size_t)m * N + n) = o;
        }
    }
}

// ---------------------------------------------------------------------------
// Attention v2 — broadcast-heavy micro-tiles, softmax fully in registers.
//
// Block: 64 q-rows of one (b,h). 256 threads = 8 warps.
// Thread (ty = warp 0..7, tx = lane 0..31) owns:
//   scores: q = ty*8 .. ty*8+7  (8 rows), s = tx (one key position), all 3 adapters
//   PV:     q = ty*8 .. ty*8+7, d = tx*2, tx*2+1
//
// Per 32-key iteration:
//   scores (z[3][8]) -> register softmax over adapters -> STS.128 P -> PV.
// All LDS is either warp-broadcast (Q rows, P rows) or conflict-free
// lane-strided (pitch 68 floats => 4-bank stride per lane across 8-lane
// LDS.128 phases).
// smem = (64 + 96 + 96) * 68 floats = 69,632 B (dynamic) -> 3 blocks/SM.
// ---------------------------------------------------------------------------
#define PITCH 68

__global__ __launch_bounds__(256, 3)
void attn2_kernel(const float* __restrict__ Q, const float* __restrict__ K,
                  const float* __restrict__ V, float* __restrict__ O)
{
    extern __shared__ float sm[];
    float* Qs = sm;                    // [64][PITCH]
    float* KV = sm + 64 * PITCH;       // [96][PITCH]   K, then reused for V
    float* Ps = KV + 96 * PITCH;       // [96][PITCH]   P[n][q]

    const int q0 = blockIdx.x * 64;
    const int h  = blockIdx.y;
    const int b  = blockIdx.z;
    const int tid = threadIdx.x;
    const int tx = tid & 31;
    const int ty = tid >> 5;

    // Load Q tile (64 rows x 64 floats)
    for (int i = tid; i < 64 * 16; i += 256) {
        int q = i >> 4, c = (i & 15) * 4;
        *(float4*)&Qs[q * PITCH + c] =
            *(const float4*)(Q + (((size_t)((b * Ss + q0 + q) * NHh + h)) << 6) + c);
    }

    float2 o[8];
#pragma unroll
    for (int i = 0; i < 8; i++) o[i] = make_float2(0.f, 0.f);

    const size_t kvHead = (size_t)h * HDd;

    for (int s0 = 0; s0 < Ss; s0 += 32) {
        __syncthreads();   // prior PV finished (covers Q load on iter 0)

        // Load K chunk: rows n = a*32+s, 64 floats each
        for (int i = tid; i < 96 * 16; i += 256) {
            int r = i >> 4, c = (i & 15) * 4;
            int a = r >> 5, s = r & 31;
            size_t base = ((size_t)((b * Aa + a) * Ss + s0 + s)) * Hh + kvHead + c;
            *(float4*)&KV[r * PITCH + c] = *(const float4*)(K + base);
        }
        __syncthreads();

        // Scores: z[a][i] = Q[q=ty*8+i] . K[a, s=tx]
        float z[3][8];
#pragma unroll
        for (int a = 0; a < 3; a++)
#pragma unroll
            for (int i = 0; i < 8; i++) z[a][i] = 0.f;

#pragma unroll 4
        for (int d4 = 0; d4 < 16; d4++) {
            float4 k0 = *(float4*)&KV[(0 * 32 + tx) * PITCH + d4 * 4];
            float4 k1 = *(float4*)&KV[(1 * 32 + tx) * PITCH + d4 * 4];
            float4 k2 = *(float4*)&KV[(2 * 32 + tx) * PITCH + d4 * 4];
#pragma unroll
            for (int i = 0; i < 8; i++) {
                float4 qv = *(float4*)&Qs[(ty * 8 + i) * PITCH + d4 * 4];
                z[0][i] += qv.x*k0.x + qv.y*k0.y + qv.z*k0.z + qv.w*k0.w;
                z[1][i] += qv.x*k1.x + qv.y*k1.y + qv.z*k1.z + qv.w*k1.w;
                z[2][i] += qv.x*k2.x + qv.y*k2.y + qv.z*k2.z + qv.w*k2.w;
            }
        }
        __syncthreads();   // everyone done reading K before V overwrites it

        // Softmax over adapters — all in registers (reuse z as p)
#pragma unroll
        for (int i = 0; i < 8; i++) {
            float z0 = z[0][i] * 0.125f;
            float z1 = z[1][i] * 0.125f;
            float z2 = z[2][i] * 0.125f;
            float m  = fmaxf(z0, fmaxf(z1, z2));
            float e0 = __expf(z0 - m);
            float e1 = __expf(z1 - m);
            float e2 = __expf(z2 - m);
            float inv = 1.f / (e0 + e1 + e2);
            z[0][i] = e0 * inv;
            z[1][i] = e1 * inv;
            z[2][i] = e2 * inv;
        }

        // Write P[n][q] (conflict-free STS.128: lane row stride = PITCH)
#pragma unroll
        for (int a = 0; a < 3; a++) {
            float4 pa = make_float4(z[a][0], z[a][1], z[a][2], z[a][3]);
            float4 pb = make_float4(z[a][4], z[a][5], z[a][6], z[a][7]);
            *(float4*)&Ps[(a * 32 + tx) * PITCH + ty * 8]     = pa;
            *(float4*)&Ps[(a * 32 + tx) * PITCH + ty * 8 + 4] = pb;
        }

        // Load V chunk into KV
        for (int i = tid; i < 96 * 16; i += 256) {
            int r = i >> 4, c = (i & 15) * 4;
            int a = r >> 5, s = r & 31;
            size_t base = ((size_t)((b * Aa + a) * Ss + s0 + s)) * Hh + kvHead + c;
            *(float4*)&KV[r * PITCH + c] = *(const float4*)(V + base);
        }
        __syncthreads();

        // PV: o[q][d] += sum_n P[n][q] * V[n][d]
#pragma unroll 8
        for (int n = 0; n < 96; n++) {
            float4 pA = *(float4*)&Ps[n * PITCH + ty * 8];
            float4 pB = *(float4*)&Ps[n * PITCH + ty * 8 + 4];
            float2 v  = *(float2*)&KV[n * PITCH + tx * 2];
            o[0].x += pA.x * v.x;  o[0].y += pA.x * v.y;
            o[1].x += pA.y * v.x;  o[1].y += pA.y * v.y;
            o[2].x += pA.z * v.x;  o[2].y += pA.z * v.y;
            o[3].x += pA.w * v.x;  o[3].y += pA.w * v.y;
            o[4].x += pB.x * v.x;  o[4].y += pB.x * v.y;
            o[5].x += pB.y * v.x;  o[5].y += pB.y * v.y;
            o[6].x += pB.z * v.x;  o[6].y += pB.z * v.y;
            o[7].x += pB.w * v.x;  o[7].y += pB.w * v.y;
        }
    }

    // Write attended [B,S,NH,HD]
#pragma unroll
    for (int i = 0; i < 8; i++) {
        int q = q0 + ty * 8 + i;
        *(float2*)(O + (((size_t)((b * Ss + q) * NHh + h)) << 6) + tx * 2) = o[i];
    }
}

// ---------------------------------------------------------------------------
// Row LayerNorm over H=768 (one block per row, 256 threads x 3 elements)
// ---------------------------------------------------------------------------
__global__ __launch_bounds__(256)
void ln_kernel(const float* __restrict__ X, const float* __restrict__ gamma,
               const float* __restrict__ beta, float* __restrict__ out)
{
    __shared__ float red[256];
    const int row = blockIdx.x;
    const int tid = threadIdx.x;
    const float* x = X + (size_t)row * Hh;

    float vals[3];
    float s = 0.f;
#pragma unroll
    for (int i = 0; i < 3; i++) {
        vals[i] = x[tid + i * 256];
        s += vals[i];
    }
    red[tid] = s;
    __syncthreads();
#pragma unroll
    for (int off = 128; off > 0; off >>= 1) {
        if (tid < off) red[tid] += red[tid + off];
        __syncthreads();
    }
    float mean = red[0] * (1.f / Hh);
    __syncthreads();

    float v = 0.f;
#pragma unroll
    for (int i = 0; i < 3; i++) {
        float d = vals[i] - mean;
        v += d * d;
    }
    red[tid] = v;
    __syncthreads();
#pragma unroll
    for (int off = 128; off > 0; off >>= 1) {
        if (tid < off) red[tid] += red[tid + off];
        __syncthreads();
    }
    float inv = rsqrtf(red[0] * (1.f / Hh) + 1e-5f);

#pragma unroll
    for (int i = 0; i < 3; i++) {
        int c = tid + i * 256;
        out[(size_t)row * Hh + c] = (vals[i] - mean) * inv * gamma[c] + beta[c];
    }
}

// Constant fill (avg_weights == 1/3 analytically: softmax over the adapter
// axis sums to 1 for every (b,h,q,s), so mean over heads then adapters = 1/A)
__global__ void fill_kernel(float* __restrict__ p, int n4, float v)
{
    int i = blockIdx.x * blockDim.x + threadIdx.x;
    if (i < n4) {
        float4 f = make_float4(v, v, v, v);
        *(float4*)(p + (size_t)i * 4) = f;
    }
}

// ---------------------------------------------------------------------------
extern "C" void kernel_launch(void* const* d_in, const int* in_sizes, int n_in,
                              void* d_out, int out_size)
{
    const float* query = (const float*)d_in[0];
    const float* adap  = (const float*)d_in[1];
    const float* Wq = (const float*)d_in[2];  const float* bq = (const float*)d_in[3];
    const float* Wk = (const float*)d_in[4];  const float* bk = (const float*)d_in[5];
    const float* Wv = (const float*)d_in[6];  const float* bv = (const float*)d_in[7];
    const float* Wo = (const float*)d_in[8];  const float* bo = (const float*)d_in[9];
    const float* gamma = (const float*)d_in[10];
    const float* beta  = (const float*)d_in[11];
    float* out = (float*)d_out;

    float *Qp, *Kp, *Vp, *Att, *Oo;
    cudaGetSymbolAddress((void**)&Qp,  g_Q);
    cudaGetSymbolAddress((void**)&Kp,  g_K);
    cudaGetSymbolAddress((void**)&Vp,  g_V);
    cudaGetSymbolAddress((void**)&Att, g_att);
    cudaGetSymbolAddress((void**)&Oo,  g_O);

    const int MQ = Bb * Ss;            // 4096
    const int MKV = Bb * Aa * Ss;      // 12288

    dim3 blk(256);
    dim3 gq(Hh / 128, MQ / 128);       // (6, 32)
    dim3 gkv(Hh / 128, MKV / 128);     // (6, 96)

    // Projections
    gemm_bias<false><<<gq,  blk>>>(query, Wq, bq, nullptr, Qp, MQ,  Hh, Hh);
    gemm_bias<false><<<gkv, blk>>>(adap,  Wk, bk, nullptr, Kp, MKV, Hh, Hh);
    gemm_bias<false><<<gkv, blk>>>(adap,  Wv, bv, nullptr, Vp, MKV, Hh, Hh);

    // Attention (dynamic smem 69,632 B -> needs opt-in above 48KB)
    const int smemBytes = (64 + 96 + 96) * PITCH * (int)sizeof(float);
    cudaFuncSetAttribute(attn2_kernel,
                         cudaFuncAttributeMaxDynamicSharedMemorySize, smemBytes);
    dim3 ga(Ss / 64, NHh, Bb);         // (16, 12, 4)
    attn2_kernel<<<ga, blk, smemBytes>>>(Qp, Kp, Vp, Att);

    // Output projection + residual
    gemm_bias<true><<<gq, blk>>>(Att, Wo, bo, query, Oo, MQ, Hh, Hh);

    // LayerNorm into first output region
    ln_kernel<<<MQ, blk>>>(Oo, gamma, beta, out);

    // avg_weights region = constant 1/3
    const int out0 = Bb * Ss * Hh;
    const int navg = out_size - out0;
    int n4 = navg / 4;
    fill_kernel<<<(n4 + 255) / 256, 256>>>(out + out0, n4, 1.0f / 3.0f);
}

// round 7
// speedup vs baseline: 2.0688x; 2.0688x over previous
#include <cuda_runtime.h>
#include <math.h>
#include <stdint.h>

// Problem constants
#define Bb  4
#define Aa  3
#define Ss  1024
#define Hh  768
#define NHh 12
#define HDd 64

// Device scratch (allocation-free rule: __device__ globals)
__device__ float g_Q  [Bb*Ss*Hh];          // Q projection  [B,S,NH,HD]
__device__ float g_K  [Bb*Aa*Ss*Hh];       // K projection  [B,A,S,NH,HD]
__device__ float g_V  [Bb*Aa*Ss*Hh];       // V projection  [B,A,S,NH,HD]
__device__ float g_att[Bb*Ss*Hh];          // attended      [B,S,NH,HD]
__device__ float g_O  [Bb*Ss*Hh];          // pre-LN (proj + residual)

// ===========================================================================
// mma.sync helpers (arch-portable: compiles for compute_103 without 'a')
// ===========================================================================
__device__ __forceinline__ uint32_t f2tf32(float x) {
    uint32_t r;
    asm("cvt.rna.tf32.f32 %0, %1;" : "=r"(r) : "f"(x));
    return r;
}

// D(16x8,f32) += A(16x8,tf32) * B(8x8,tf32)
__device__ __forceinline__ void mma_tf32(float c[4], const uint32_t a[4],
                                         const uint32_t b[2]) {
    asm volatile(
        "mma.sync.aligned.m16n8k8.row.col.f32.tf32.tf32.f32 "
        "{%0,%1,%2,%3}, {%4,%5,%6,%7}, {%8,%9}, {%0,%1,%2,%3};"
        : "+f"(c[0]), "+f"(c[1]), "+f"(c[2]), "+f"(c[3])
        : "r"(a[0]), "r"(a[1]), "r"(a[2]), "r"(a[3]), "r"(b[0]), "r"(b[1]));
}

// ===========================================================================
// GEMM via mma.sync tf32: out[m,n] = sum_k X[m,k]*W[n,k] + bias[n] (+res)
// BM=BN=128, BK=16, 256 threads = 8 warps (4 in M x 2 in N, warp tile 32x64).
// Smem pitch 20 floats -> all fragment loads are bank-conflict-free.
// ===========================================================================
template<bool ADD>
__global__ __launch_bounds__(256)
void gemm_mma(const float* __restrict__ X, const float* __restrict__ W,
              const float* __restrict__ bias, const float* __restrict__ res,
              float* __restrict__ out, int M, int N, int K)
{
    __shared__ float As[128 * 20];
    __shared__ float Bs[128 * 20];
    const uint32_t* Au = (const uint32_t*)As;
    const uint32_t* Bu = (const uint32_t*)Bs;

    const int tid  = threadIdx.x;
    const int lane = tid & 31;
    const int gid  = lane >> 2;
    const int tig  = lane & 3;
    const int wid  = tid >> 5;
    const int wm   = (wid >> 1) * 32;    // 0,32,64,96
    const int wn   = (wid & 1) * 64;     // 0,64
    const int m0   = blockIdx.y * 128;
    const int n0   = blockIdx.x * 128;

    float acc[2][8][4];
#pragma unroll
    for (int mi = 0; mi < 2; mi++)
#pragma unroll
        for (int ni = 0; ni < 8; ni++)
#pragma unroll
            for (int j = 0; j < 4; j++) acc[mi][ni][j] = 0.f;

    for (int k0 = 0; k0 < K; k0 += 16) {
        // cooperative load + tf32 conversion (pitch 20)
#pragma unroll
        for (int p = 0; p < 2; p++) {
            int i  = p * 256 + tid;
            int r  = i >> 2;
            int c4 = (i & 3) * 4;
            float4 xv = *(const float4*)(X + (size_t)(m0 + r) * K + k0 + c4);
            float4 wv = *(const float4*)(W + (size_t)(n0 + r) * K + k0 + c4);
            uint32_t* ax = (uint32_t*)&As[r * 20 + c4];
            ax[0] = f2tf32(xv.x); ax[1] = f2tf32(xv.y);
            ax[2] = f2tf32(xv.z); ax[3] = f2tf32(xv.w);
            uint32_t* bx = (uint32_t*)&Bs[r * 20 + c4];
            bx[0] = f2tf32(wv.x); bx[1] = f2tf32(wv.y);
            bx[2] = f2tf32(wv.z); bx[3] = f2tf32(wv.w);
        }
        __syncthreads();

#pragma unroll
        for (int ks = 0; ks < 2; ks++) {
            const int kk = ks * 8;
            uint32_t a[2][4], b[8][2];
#pragma unroll
            for (int mi = 0; mi < 2; mi++) {
                int rb = wm + mi * 16;
                a[mi][0] = Au[(rb + gid)     * 20 + kk + tig];
                a[mi][1] = Au[(rb + gid + 8) * 20 + kk + tig];
                a[mi][2] = Au[(rb + gid)     * 20 + kk + tig + 4];
                a[mi][3] = Au[(rb + gid + 8) * 20 + kk + tig + 4];
            }
#pragma unroll
            for (int ni = 0; ni < 8; ni++) {
                int nb = wn + ni * 8 + gid;
                b[ni][0] = Bu[nb * 20 + kk + tig];
                b[ni][1] = Bu[nb * 20 + kk + tig + 4];
            }
#pragma unroll
            for (int mi = 0; mi < 2; mi++)
#pragma unroll
                for (int ni = 0; ni < 8; ni++)
                    mma_tf32(acc[mi][ni], a[mi], b[ni]);
        }
        __syncthreads();
    }

    // Epilogue
#pragma unroll
    for (int mi = 0; mi < 2; mi++) {
        int r0 = m0 + wm + mi * 16 + gid;
        int r1 = r0 + 8;
#pragma unroll
        for (int ni = 0; ni < 8; ni++) {
            int col = n0 + wn + ni * 8 + 2 * tig;
            float b0 = bias[col], b1 = bias[col + 1];
            float2 v0 = make_float2(acc[mi][ni][0] + b0, acc[mi][ni][1] + b1);
            float2 v1 = make_float2(acc[mi][ni][2] + b0, acc[mi][ni][3] + b1);
            if (ADD) {
                float2 ra = *(const float2*)(res + (size_t)r0 * N + col);
                float2 rb = *(const float2*)(res + (size_t)r1 * N + col);
                v0.x += ra.x; v0.y += ra.y;
                v1.x += rb.x; v1.y += rb.y;
            }
            *(float2*)(out + (size_t)r0 * N + col) = v0;
            *(float2*)(out + (size_t)r1 * N + col) = v1;
        }
    }
}

// ===========================================================================
// Attention v3 — scores and PV on mma.sync tf32; softmax in registers.
//
// Block: 64 q-rows of one (b,h), 256 threads = 8 warps (4 in q, 2 in s/d).
// Per 32-key chunk (96 rows with adapters):
//   scores: per adapter a, C[a] = Q(16q x 64d) . K^T  -> thread holds all 3
//           adapter scores for its (q,s) positions -> register softmax.
//   P -> smem (tf32), PV: O += P(16q x 96n) . V(96n x 32d) via mma.
// Pitches: Q/K 68, V 72, P 100 -> every fragment-read pattern bank-free.
// smem = (64*68 + 96*68 + 96*72 + 64*100)*4 = 96768 B -> 2 blocks/SM.
// ===========================================================================
#define QP 68
#define KP 68
#define VP 72
#define PP 100
#define OFF_Q 0
#define OFF_K (64 * QP)            // 4352
#define OFF_V (OFF_K + 96 * KP)    // 10880
#define OFF_P (OFF_V + 96 * VP)    // 17792
#define ATTN_SMEM ((OFF_P + 64 * PP) * 4)   // 96768 B

__global__ __launch_bounds__(256, 2)
void attn3_kernel(const float* __restrict__ Q, const float* __restrict__ K,
                  const float* __restrict__ V, float* __restrict__ O)
{
    extern __shared__ float sm[];
    uint32_t* smU = (uint32_t*)sm;

    const int q0  = blockIdx.x * 64;
    const int h   = blockIdx.y;
    const int b   = blockIdx.z;
    const int tid  = threadIdx.x;
    const int lane = tid & 31;
    const int gid  = lane >> 2;
    const int tig  = lane & 3;
    const int wid  = tid >> 5;
    const int wm   = (wid >> 1) * 16;   // q rows: 0,16,32,48
    const int wns  = (wid & 1) * 16;    // key split for scores: 0,16
    const int wnd  = (wid & 1) * 32;    // d split for PV: 0,32

    // Load Q tile (tf32-converted), pitch QP
    for (int i = tid; i < 64 * 16; i += 256) {
        int q = i >> 4, c4 = (i & 15) * 4;
        float4 v = *(const float4*)(Q + (((size_t)((b * Ss + q0 + q) * NHh + h)) << 6) + c4);
        uint32_t* d = &smU[OFF_Q + q * QP + c4];
        d[0] = f2tf32(v.x); d[1] = f2tf32(v.y);
        d[2] = f2tf32(v.z); d[3] = f2tf32(v.w);
    }

    float co[4][4];
#pragma unroll
    for (int ni = 0; ni < 4; ni++)
#pragma unroll
        for (int j = 0; j < 4; j++) co[ni][j] = 0.f;

    const size_t kvHead = (size_t)h * HDd;

    for (int s0 = 0; s0 < Ss; s0 += 32) {
        __syncthreads();   // prior PV done (covers Q load on iter 0)

        // Load K (pitch KP) and V (pitch VP), tf32-converted
        for (int i = tid; i < 96 * 16; i += 256) {
            int r = i >> 4, c4 = (i & 15) * 4;
            int a = r >> 5, s = r & 31;
            size_t base = ((size_t)((b * Aa + a) * Ss + s0 + s)) * Hh + kvHead + c4;
            float4 kv = *(const float4*)(K + base);
            uint32_t* dk = &smU[OFF_K + r * KP + c4];
            dk[0] = f2tf32(kv.x); dk[1] = f2tf32(kv.y);
            dk[2] = f2tf32(kv.z); dk[3] = f2tf32(kv.w);
            float4 vv = *(const float4*)(V + base);
            uint32_t* dv = &smU[OFF_V + r * VP + c4];
            dv[0] = f2tf32(vv.x); dv[1] = f2tf32(vv.y);
            dv[2] = f2tf32(vv.z); dv[3] = f2tf32(vv.w);
        }
        __syncthreads();

        // ---- scores: cs[a][ni] = Q(16x64) . K_a^T(64 x 16-slice) ----
        float cs[3][2][4];
#pragma unroll
        for (int a = 0; a < 3; a++)
#pragma unroll
            for (int ni = 0; ni < 2; ni++)
#pragma unroll
                for (int j = 0; j < 4; j++) cs[a][ni][j] = 0.f;

#pragma unroll
        for (int ks = 0; ks < 8; ks++) {
            const int kk = ks * 8;
            uint32_t a[4];
            a[0] = smU[OFF_Q + (wm + gid)     * QP + kk + tig];
            a[1] = smU[OFF_Q + (wm + gid + 8) * QP + kk + tig];
            a[2] = smU[OFF_Q + (wm + gid)     * QP + kk + tig + 4];
            a[3] = smU[OFF_Q + (wm + gid + 8) * QP + kk + tig + 4];
#pragma unroll
            for (int ad = 0; ad < 3; ad++)
#pragma unroll
                for (int ni = 0; ni < 2; ni++) {
                    int krow = ad * 32 + wns + ni * 8 + gid;
                    uint32_t bb[2];
                    bb[0] = smU[OFF_K + krow * KP + kk + tig];
                    bb[1] = smU[OFF_K + krow * KP + kk + tig + 4];
                    mma_tf32(cs[ad][ni], a, bb);
                }
        }

        // ---- softmax over adapters (registers), write P (tf32) ----
#pragma unroll
        for (int ni = 0; ni < 2; ni++)
#pragma unroll
            for (int pos = 0; pos < 4; pos++) {
                float z0 = cs[0][ni][pos] * 0.125f;
                float z1 = cs[1][ni][pos] * 0.125f;
                float z2 = cs[2][ni][pos] * 0.125f;
                float m  = fmaxf(z0, fmaxf(z1, z2));
                float e0 = __expf(z0 - m);
                float e1 = __expf(z1 - m);
                float e2 = __expf(z2 - m);
                float inv = 1.f / (e0 + e1 + e2);
                int q  = wm + gid + ((pos >> 1) << 3);
                int sl = wns + ni * 8 + 2 * tig + (pos & 1);
                smU[OFF_P + q * PP +      sl] = f2tf32(e0 * inv);
                smU[OFF_P + q * PP + 32 + sl] = f2tf32(e1 * inv);
                smU[OFF_P + q * PP + 64 + sl] = f2tf32(e2 * inv);
            }
        __syncthreads();   // P complete (both wn warps of each wm row group)

        // ---- PV: co += P(16q x 96n) . V(96n x 32d) ----
#pragma unroll
        for (int kn = 0; kn < 12; kn++) {
            const int kk = kn * 8;
            uint32_t a[4];
            a[0] = smU[OFF_P + (wm + gid)     * PP + kk + tig];
            a[1] = smU[OFF_P + (wm + gid + 8) * PP + kk + tig];
            a[2] = smU[OFF_P + (wm + gid)     * PP + kk + tig + 4];
            a[3] = smU[OFF_P + (wm + gid + 8) * PP + kk + tig + 4];
#pragma unroll
            for (int ni = 0; ni < 4; ni++) {
                int d = wnd + ni * 8 + gid;
                uint32_t bb[2];
                bb[0] = smU[OFF_V + (kk + tig)     * VP + d];
                bb[1] = smU[OFF_V + (kk + tig + 4) * VP + d];
                mma_tf32(co[ni], a, bb);
            }
        }
    }

    // Write attended [B,S,NH,HD]
#pragma unroll
    for (int ni = 0; ni < 4; ni++) {
        int d  = wnd + ni * 8 + 2 * tig;
        int r0 = q0 + wm + gid;
        int r1 = r0 + 8;
        *(float2*)(O + (((size_t)((b * Ss + r0) * NHh + h)) << 6) + d) =
            make_float2(co[ni][0], co[ni][1]);
        *(float2*)(O + (((size_t)((b * Ss + r1) * NHh + h)) << 6) + d) =
            make_float2(co[ni][2], co[ni][3]);
    }
}

// ---------------------------------------------------------------------------
// Row LayerNorm over H=768
// ---------------------------------------------------------------------------
__global__ __launch_bounds__(256)
void ln_kernel(const float* __restrict__ X, const float* __restrict__ gamma,
               const float* __restrict__ beta, float* __restrict__ out)
{
    __shared__ float red[256];
    const int row = blockIdx.x;
    const int tid = threadIdx.x;
    const float* x = X + (size_t)row * Hh;

    float vals[3];
    float s = 0.f;
#pragma unroll
    for (int i = 0; i < 3; i++) {
        vals[i] = x[tid + i * 256];
        s += vals[i];
    }
    red[tid] = s;
    __syncthreads();
#pragma unroll
    for (int off = 128; off > 0; off >>= 1) {
        if (tid < off) red[tid] += red[tid + off];
        __syncthreads();
    }
    float mean = red[0] * (1.f / Hh);
    __syncthreads();

    float v = 0.f;
#pragma unroll
    for (int i = 0; i < 3; i++) {
        float d = vals[i] - mean;
        v += d * d;
    }
    red[tid] = v;
    __syncthreads();
#pragma unroll
    for (int off = 128; off > 0; off >>= 1) {
        if (tid < off) red[tid] += red[tid + off];
        __syncthreads();
    }
    float inv = rsqrtf(red[0] * (1.f / Hh) + 1e-5f);

#pragma unroll
    for (int i = 0; i < 3; i++) {
        int c = tid + i * 256;
        out[(size_t)row * Hh + c] = (vals[i] - mean) * inv * gamma[c] + beta[c];
    }
}

// avg_weights == 1/3 analytically (softmax over the adapter axis sums to 1)
__global__ void fill_kernel(float* __restrict__ p, int n4, float v)
{
    int i = blockIdx.x * blockDim.x + threadIdx.x;
    if (i < n4) {
        float4 f = make_float4(v, v, v, v);
        *(float4*)(p + (size_t)i * 4) = f;
    }
}

// ---------------------------------------------------------------------------
extern "C" void kernel_launch(void* const* d_in, const int* in_sizes, int n_in,
                              void* d_out, int out_size)
{
    const float* query = (const float*)d_in[0];
    const float* adap  = (const float*)d_in[1];
    const float* Wq = (const float*)d_in[2];  const float* bq = (const float*)d_in[3];
    const float* Wk = (const float*)d_in[4];  const float* bk = (const float*)d_in[5];
    const float* Wv = (const float*)d_in[6];  const float* bv = (const float*)d_in[7];
    const float* Wo = (const float*)d_in[8];  const float* bo = (const float*)d_in[9];
    const float* gamma = (const float*)d_in[10];
    const float* beta  = (const float*)d_in[11];
    float* out = (float*)d_out;

    float *Qp, *Kp, *Vp, *Att, *Oo;
    cudaGetSymbolAddress((void**)&Qp,  g_Q);
    cudaGetSymbolAddress((void**)&Kp,  g_K);
    cudaGetSymbolAddress((void**)&Vp,  g_V);
    cudaGetSymbolAddress((void**)&Att, g_att);
    cudaGetSymbolAddress((void**)&Oo,  g_O);

    const int MQ = Bb * Ss;            // 4096
    const int MKV = Bb * Aa * Ss;      // 12288

    dim3 blk(256);
    dim3 gq(Hh / 128, MQ / 128);       // (6, 32)
    dim3 gkv(Hh / 128, MKV / 128);     // (6, 96)

    // Projections (mma.sync tf32)
    gemm_mma<false><<<gq,  blk>>>(query, Wq, bq, nullptr, Qp, MQ,  Hh, Hh);
    gemm_mma<false><<<gkv, blk>>>(adap,  Wk, bk, nullptr, Kp, MKV, Hh, Hh);
    gemm_mma<false><<<gkv, blk>>>(adap,  Wv, bv, nullptr, Vp, MKV, Hh, Hh);

    // Attention (mma.sync tf32)
    cudaFuncSetAttribute(attn3_kernel,
                         cudaFuncAttributeMaxDynamicSharedMemorySize, ATTN_SMEM);
    dim3 ga(Ss / 64, NHh, Bb);         // (16, 12, 4)
    attn3_kernel<<<ga, blk, ATTN_SMEM>>>(Qp, Kp, Vp, Att);

    // Output projection + residual (mma.sync tf32)
    gemm_mma<true><<<gq, blk>>>(Att, Wo, bo, query, Oo, MQ, Hh, Hh);

    // LayerNorm into first output region
    ln_kernel<<<MQ, blk>>>(Oo, gamma, beta, out);

    // avg_weights region = constant 1/3
    const int out0 = Bb * Ss * Hh;
    const int navg = out_size - out0;
    int n4 = navg / 4;
    fill_kernel<<<(n4 + 255) / 256, 256>>>(out + out0, n4, 1.0f / 3.0f);
}

// round 8
// speedup vs baseline: 2.2506x; 1.0879x over previous
#include <cuda_runtime.h>
#include <math.h>
#include <stdint.h>

// Problem constants
#define Bb  4
#define Aa  3
#define Ss  1024
#define Hh  768
#define NHh 12
#define HDd 64

// Device scratch (allocation-free rule: __device__ globals)
__device__ float g_Q  [Bb*Ss*Hh];          // Q projection  [B,S,NH,HD]
__device__ float g_K  [Bb*Aa*Ss*Hh];       // K projection  [B,A,S,NH,HD]
__device__ float g_V  [Bb*Aa*Ss*Hh];       // V projection  [B,A,S,NH,HD]
__device__ float g_att[Bb*Ss*Hh];          // attended      [B,S,NH,HD]
__device__ float g_O  [Bb*Ss*Hh];          // pre-LN (proj + residual)

// ===========================================================================
// mma.sync helpers (arch-portable: compiles for compute_103 without 'a')
// ===========================================================================
__device__ __forceinline__ uint32_t f2tf32(float x) {
    uint32_t r;
    asm("cvt.rna.tf32.f32 %0, %1;" : "=r"(r) : "f"(x));
    return r;
}

// D(16x8,f32) += A(16x8,tf32) * B(8x8,tf32)
__device__ __forceinline__ void mma_tf32(float c[4], const uint32_t a[4],
                                         const uint32_t b[2]) {
    asm volatile(
        "mma.sync.aligned.m16n8k8.row.col.f32.tf32.tf32.f32 "
        "{%0,%1,%2,%3}, {%4,%5,%6,%7}, {%8,%9}, {%0,%1,%2,%3};"
        : "+f"(c[0]), "+f"(c[1]), "+f"(c[2]), "+f"(c[3])
        : "r"(a[0]), "r"(a[1]), "r"(a[2]), "r"(a[3]), "r"(b[0]), "r"(b[1]));
}

// ===========================================================================
// GEMM via mma.sync tf32 with register-staged double buffering.
// BM=BN=128, BK=16, 256 threads = 8 warps (4 in M x 2 in N, warp tile 32x64).
// Smem pitch 20 floats -> fragment loads bank-conflict-free.
// One __syncthreads per k-chunk; next chunk's LDG overlaps current MMAs.
// ===========================================================================
template<bool ADD>
__global__ __launch_bounds__(256)
void gemm_mma(const float* __restrict__ X, const float* __restrict__ W,
              const float* __restrict__ bias, const float* __restrict__ res,
              float* __restrict__ out, int M, int N, int K)
{
    __shared__ float As[2][128 * 20];
    __shared__ float Bs[2][128 * 20];

    const int tid  = threadIdx.x;
    const int lane = tid & 31;
    const int gid  = lane >> 2;
    const int tig  = lane & 3;
    const int wid  = tid >> 5;
    const int wm   = (wid >> 1) * 32;    // 0,32,64,96
    const int wn   = (wid & 1) * 64;     // 0,64
    const int m0   = blockIdx.y * 128;
    const int n0   = blockIdx.x * 128;
    const int lr   = tid >> 2;           // load row 0..63 (+64 for p=1)
    const int lc   = (tid & 3) * 4;      // load col 0..12

    float acc[2][8][4];
#pragma unroll
    for (int mi = 0; mi < 2; mi++)
#pragma unroll
        for (int ni = 0; ni < 8; ni++)
#pragma unroll
            for (int j = 0; j < 4; j++) acc[mi][ni][j] = 0.f;

    float4 xr[2], wr[2];

    // prologue: load chunk 0, store to buffer 0
#pragma unroll
    for (int p = 0; p < 2; p++) {
        xr[p] = *(const float4*)(X + (size_t)(m0 + lr + p * 64) * K + lc);
        wr[p] = *(const float4*)(W + (size_t)(n0 + lr + p * 64) * K + lc);
    }
#pragma unroll
    for (int p = 0; p < 2; p++) {
        uint32_t* ax = (uint32_t*)&As[0][(lr + p * 64) * 20 + lc];
        ax[0] = f2tf32(xr[p].x); ax[1] = f2tf32(xr[p].y);
        ax[2] = f2tf32(xr[p].z); ax[3] = f2tf32(xr[p].w);
        uint32_t* bx = (uint32_t*)&Bs[0][(lr + p * 64) * 20 + lc];
        bx[0] = f2tf32(wr[p].x); bx[1] = f2tf32(wr[p].y);
        bx[2] = f2tf32(wr[p].z); bx[3] = f2tf32(wr[p].w);
    }
    __syncthreads();

    const int NK = K / 16;   // 48
    for (int kc = 0; kc < NK; kc++) {
        const int cur = kc & 1;

        // prefetch next chunk into registers (overlaps the MMAs below)
        if (kc + 1 < NK) {
            const int k0 = (kc + 1) * 16;
#pragma unroll
            for (int p = 0; p < 2; p++) {
                xr[p] = *(const float4*)(X + (size_t)(m0 + lr + p * 64) * K + k0 + lc);
                wr[p] = *(const float4*)(W + (size_t)(n0 + lr + p * 64) * K + k0 + lc);
            }
        }

        const uint32_t* Au = (const uint32_t*)As[cur];
        const uint32_t* Bu = (const uint32_t*)Bs[cur];
#pragma unroll
        for (int ks = 0; ks < 2; ks++) {
            const int kk = ks * 8;
            uint32_t a[2][4], b[8][2];
#pragma unroll
            for (int mi = 0; mi < 2; mi++) {
                int rb = wm + mi * 16;
                a[mi][0] = Au[(rb + gid)     * 20 + kk + tig];
                a[mi][1] = Au[(rb + gid + 8) * 20 + kk + tig];
                a[mi][2] = Au[(rb + gid)     * 20 + kk + tig + 4];
                a[mi][3] = Au[(rb + gid + 8) * 20 + kk + tig + 4];
            }
#pragma unroll
            for (int ni = 0; ni < 8; ni++) {
                int nb = wn + ni * 8 + gid;
                b[ni][0] = Bu[nb * 20 + kk + tig];
                b[ni][1] = Bu[nb * 20 + kk + tig + 4];
            }
#pragma unroll
            for (int mi = 0; mi < 2; mi++)
#pragma unroll
                for (int ni = 0; ni < 8; ni++)
                    mma_tf32(acc[mi][ni], a[mi], b[ni]);
        }

        // stage next chunk into the other buffer (safe: its readers finished
        // before the sync that ended iteration kc-1)
        if (kc + 1 < NK) {
            const int nxt = cur ^ 1;
#pragma unroll
            for (int p = 0; p < 2; p++) {
                uint32_t* ax = (uint32_t*)&As[nxt][(lr + p * 64) * 20 + lc];
                ax[0] = f2tf32(xr[p].x); ax[1] = f2tf32(xr[p].y);
                ax[2] = f2tf32(xr[p].z); ax[3] = f2tf32(xr[p].w);
                uint32_t* bx = (uint32_t*)&Bs[nxt][(lr + p * 64) * 20 + lc];
                bx[0] = f2tf32(wr[p].x); bx[1] = f2tf32(wr[p].y);
                bx[2] = f2tf32(wr[p].z); bx[3] = f2tf32(wr[p].w);
            }
        }
        __syncthreads();
    }

    // Epilogue
#pragma unroll
    for (int mi = 0; mi < 2; mi++) {
        int r0 = m0 + wm + mi * 16 + gid;
        int r1 = r0 + 8;
#pragma unroll
        for (int ni = 0; ni < 8; ni++) {
            int col = n0 + wn + ni * 8 + 2 * tig;
            float b0 = bias[col], b1 = bias[col + 1];
            float2 v0 = make_float2(acc[mi][ni][0] + b0, acc[mi][ni][1] + b1);
            float2 v1 = make_float2(acc[mi][ni][2] + b0, acc[mi][ni][3] + b1);
            if (ADD) {
                float2 ra = *(const float2*)(res + (size_t)r0 * N + col);
                float2 rb = *(const float2*)(res + (size_t)r1 * N + col);
                v0.x += ra.x; v0.y += ra.y;
                v1.x += rb.x; v1.y += rb.y;
            }
            *(float2*)(out + (size_t)r0 * N + col) = v0;
            *(float2*)(out + (size_t)r1 * N + col) = v1;
        }
    }
}

// ===========================================================================
// Attention v4 — P never leaves registers.
//
// Block: 64 q x (b,h), 256 threads = 8 warps. Warp (wm = (wid>>1)*16 q-rows,
// ws = wid&1 key-half). Per 32-key chunk the warp owns keys
// [ws*16, ws*16+16) for all 3 adapters (48 of 96 k-rows) and the FULL d=64.
//
// Fragment identity: scores C-frag {c0,c1,c2,c3} = P at (q,2t),(q,2t+1),
// (q+8,2t),(q+8,2t+1). With logical key order sigma = [0,2,4,6,1,3,5,7]
// inside each 8-key group, the PV A-frag is exactly {c0,c2,c1,c3}, and V
// B-frags read smem rows base+2*tig and base+2*tig+1 (VP=68 -> bank-free).
//
// Each warp accumulates partial O (16q x 64d) over its key half; the two
// halves are summed once per block through smem at the end.
// Q fragments live in registers for the whole block (no Q smem).
// smem = 96*68*2 floats = 52,224 B -> 2 blocks/SM (reg-limited).
// ===========================================================================
#define KP 68
#define VP 68
#define ATTN_SMEM ((96 * KP + 96 * VP) * 4)   // 52,224 B

__global__ __launch_bounds__(256, 2)
void attn4_kernel(const float* __restrict__ Q, const float* __restrict__ K,
                  const float* __restrict__ V, float* __restrict__ O)
{
    extern __shared__ float sm[];
    uint32_t* smU = (uint32_t*)sm;
    const int OFFV = 96 * KP;

    const int q0  = blockIdx.x * 64;
    const int h   = blockIdx.y;
    const int b   = blockIdx.z;
    const int tid  = threadIdx.x;
    const int lane = tid & 31;
    const int gid  = lane >> 2;
    const int tig  = lane & 3;
    const int wid  = tid >> 5;
    const int wm   = (wid >> 1) * 16;   // q rows: 0,16,32,48
    const int ws   = wid & 1;           // key half: 0 or 1

    // Q fragments in registers for all 8 k-groups (whole head dim)
    uint32_t qf[8][4];
    {
        const float* Qb = Q + (((size_t)((b * Ss + q0 + wm) * NHh + h)) << 6);
#pragma unroll
        for (int ks = 0; ks < 8; ks++) {
            int c = ks * 8 + tig;
            qf[ks][0] = f2tf32(Qb[(size_t)gid * 768 + c]);
            qf[ks][1] = f2tf32(Qb[(size_t)(gid + 8) * 768 + c]);
            qf[ks][2] = f2tf32(Qb[(size_t)gid * 768 + c + 4]);
            qf[ks][3] = f2tf32(Qb[(size_t)(gid + 8) * 768 + c + 4]);
        }
    }

    float co[8][4];
#pragma unroll
    for (int nd = 0; nd < 8; nd++)
#pragma unroll
        for (int j = 0; j < 4; j++) co[nd][j] = 0.f;

    const size_t kvHead = (size_t)h * HDd;

    for (int s0 = 0; s0 < Ss; s0 += 32) {
        __syncthreads();   // prior chunk's PV reads finished

        // Load K and V (tf32-converted), pitch 68
        for (int i = tid; i < 96 * 16; i += 256) {
            int r = i >> 4, c4 = (i & 15) * 4;
            int a = r >> 5, s = r & 31;
            size_t base = ((size_t)((b * Aa + a) * Ss + s0 + s)) * Hh + kvHead + c4;
            float4 kv = *(const float4*)(K + base);
            uint32_t* dk = &smU[r * KP + c4];
            dk[0] = f2tf32(kv.x); dk[1] = f2tf32(kv.y);
            dk[2] = f2tf32(kv.z); dk[3] = f2tf32(kv.w);
            float4 vv = *(const float4*)(V + base);
            uint32_t* dv = &smU[OFFV + r * VP + c4];
            dv[0] = f2tf32(vv.x); dv[1] = f2tf32(vv.y);
            dv[2] = f2tf32(vv.z); dv[3] = f2tf32(vv.w);
        }
        __syncthreads();

        // ---- scores: cs[ad][ni] = Q(16x64) . K_ad^T (16-key slice) ----
        float cs[3][2][4];
#pragma unroll
        for (int ad = 0; ad < 3; ad++)
#pragma unroll
            for (int ni = 0; ni < 2; ni++)
#pragma unroll
                for (int j = 0; j < 4; j++) cs[ad][ni][j] = 0.f;

#pragma unroll
        for (int ks = 0; ks < 8; ks++) {
            const int kk = ks * 8;
#pragma unroll
            for (int ad = 0; ad < 3; ad++)
#pragma unroll
                for (int ni = 0; ni < 2; ni++) {
                    int krow = ad * 32 + ws * 16 + ni * 8 + gid;
                    uint32_t bb[2];
                    bb[0] = smU[krow * KP + kk + tig];
                    bb[1] = smU[krow * KP + kk + tig + 4];
                    mma_tf32(cs[ad][ni], qf[ks], bb);
                }
        }

        // ---- softmax over adapters in registers; keep P as tf32 bits ----
#pragma unroll
        for (int ni = 0; ni < 2; ni++)
#pragma unroll
            for (int pos = 0; pos < 4; pos++) {
                float z0 = cs[0][ni][pos] * 0.125f;
                float z1 = cs[1][ni][pos] * 0.125f;
                float z2 = cs[2][ni][pos] * 0.125f;
                float m  = fmaxf(z0, fmaxf(z1, z2));
                float e0 = __expf(z0 - m);
                float e1 = __expf(z1 - m);
                float e2 = __expf(z2 - m);
                float inv = 1.f / (e0 + e1 + e2);
                cs[0][ni][pos] = __uint_as_float(f2tf32(e0 * inv));
                cs[1][ni][pos] = __uint_as_float(f2tf32(e1 * inv));
                cs[2][ni][pos] = __uint_as_float(f2tf32(e2 * inv));
            }

        // ---- PV: co += P(16q x 48n) . V(48n x 64d), P from registers ----
#pragma unroll
        for (int ad = 0; ad < 3; ad++)
#pragma unroll
            for (int ni = 0; ni < 2; ni++) {
                uint32_t A[4];
                A[0] = __float_as_uint(cs[ad][ni][0]);
                A[1] = __float_as_uint(cs[ad][ni][2]);
                A[2] = __float_as_uint(cs[ad][ni][1]);
                A[3] = __float_as_uint(cs[ad][ni][3]);
                const int base = ad * 32 + ws * 16 + ni * 8;
                const uint32_t* v0 = &smU[OFFV + (base + 2 * tig)     * VP + gid];
                const uint32_t* v1 = &smU[OFFV + (base + 2 * tig + 1) * VP + gid];
#pragma unroll
                for (int nd = 0; nd < 8; nd++) {
                    uint32_t bb[2] = { v0[nd * 8], v1[nd * 8] };
                    mma_tf32(co[nd], A, bb);
                }
            }
    }

    // ---- cross-half reduction (ws=1 partials -> ws=0) and writeout ----
    __syncthreads();
    float* red = sm;            // reuse K region; 64 rows x pitch 66 = 16.9KB
    const int wmg = wid >> 1;
    if (ws == 1) {
#pragma unroll
        for (int nd = 0; nd < 8; nd++) {
            int c = nd * 8 + 2 * tig;
            *(float2*)&red[(wmg * 16 + gid) * 66 + c] =
                make_float2(co[nd][0], co[nd][1]);
            *(float2*)&red[(wmg * 16 + gid + 8) * 66 + c] =
                make_float2(co[nd][2], co[nd][3]);
        }
    }
    __syncthreads();
    if (ws == 0) {
#pragma unroll
        for (int nd = 0; nd < 8; nd++) {
            int c = nd * 8 + 2 * tig;
            float2 r0 = *(float2*)&red[(wmg * 16 + gid) * 66 + c];
            float2 r1 = *(float2*)&red[(wmg * 16 + gid + 8) * 66 + c];
            int q = q0 + wm + gid;
            *(float2*)(O + (((size_t)((b * Ss + q) * NHh + h)) << 6) + c) =
                make_float2(co[nd][0] + r0.x, co[nd][1] + r0.y);
            *(float2*)(O + (((size_t)((b * Ss + q + 8) * NHh + h)) << 6) + c) =
                make_float2(co[nd][2] + r1.x, co[nd][3] + r1.y);
        }
    }
}

// ---------------------------------------------------------------------------
// Row LayerNorm over H=768
// ---------------------------------------------------------------------------
__global__ __launch_bounds__(256)
void ln_kernel(const float* __restrict__ X, const float* __restrict__ gamma,
               const float* __restrict__ beta, float* __restrict__ out)
{
    __shared__ float red[256];
    const int row = blockIdx.x;
    const int tid = threadIdx.x;
    const float* x = X + (size_t)row * Hh;

    float vals[3];
    float s = 0.f;
#pragma unroll
    for (int i = 0; i < 3; i++) {
        vals[i] = x[tid + i * 256];
        s += vals[i];
    }
    red[tid] = s;
    __syncthreads();
#pragma unroll
    for (int off = 128; off > 0; off >>= 1) {
        if (tid < off) red[tid] += red[tid + off];
        __syncthreads();
    }
    float mean = red[0] * (1.f / Hh);
    __syncthreads();

    float v = 0.f;
#pragma unroll
    for (int i = 0; i < 3; i++) {
        float d = vals[i] - mean;
        v += d * d;
    }
    red[tid] = v;
    __syncthreads();
#pragma unroll
    for (int off = 128; off > 0; off >>= 1) {
        if (tid < off) red[tid] += red[tid + off];
        __syncthreads();
    }
    float inv = rsqrtf(red[0] * (1.f / Hh) + 1e-5f);

#pragma unroll
    for (int i = 0; i < 3; i++) {
        int c = tid + i * 256;
        out[(size_t)row * Hh + c] = (vals[i] - mean) * inv * gamma[c] + beta[c];
    }
}

// avg_weights == 1/3 analytically (softmax over the adapter axis sums to 1)
__global__ void fill_kernel(float* __restrict__ p, int n4, float v)
{
    int i = blockIdx.x * blockDim.x + threadIdx.x;
    if (i < n4) {
        float4 f = make_float4(v, v, v, v);
        *(float4*)(p + (size_t)i * 4) = f;
    }
}

// ---------------------------------------------------------------------------
extern "C" void kernel_launch(void* const* d_in, const int* in_sizes, int n_in,
                              void* d_out, int out_size)
{
    const float* query = (const float*)d_in[0];
    const float* adap  = (const float*)d_in[1];
    const float* Wq = (const float*)d_in[2];  const float* bq = (const float*)d_in[3];
    const float* Wk = (const float*)d_in[4];  const float* bk = (const float*)d_in[5];
    const float* Wv = (const float*)d_in[6];  const float* bv = (const float*)d_in[7];
    const float* Wo = (const float*)d_in[8];  const float* bo = (const float*)d_in[9];
    const float* gamma = (const float*)d_in[10];
    const float* beta  = (const float*)d_in[11];
    float* out = (float*)d_out;

    float *Qp, *Kp, *Vp, *Att, *Oo;
    cudaGetSymbolAddress((void**)&Qp,  g_Q);
    cudaGetSymbolAddress((void**)&Kp,  g_K);
    cudaGetSymbolAddress((void**)&Vp,  g_V);
    cudaGetSymbolAddress((void**)&Att, g_att);
    cudaGetSymbolAddress((void**)&Oo,  g_O);

    const int MQ = Bb * Ss;            // 4096
    const int MKV = Bb * Aa * Ss;      // 12288

    dim3 blk(256);
    dim3 gq(Hh / 128, MQ / 128);       // (6, 32)
    dim3 gkv(Hh / 128, MKV / 128);     // (6, 96)

    // Projections (mma.sync tf32, double-buffered)
    gemm_mma<false><<<gq,  blk>>>(query, Wq, bq, nullptr, Qp, MQ,  Hh, Hh);
    gemm_mma<false><<<gkv, blk>>>(adap,  Wk, bk, nullptr, Kp, MKV, Hh, Hh);
    gemm_mma<false><<<gkv, blk>>>(adap,  Wv, bv, nullptr, Vp, MKV, Hh, Hh);

    // Attention (mma.sync tf32, register-resident P)
    cudaFuncSetAttribute(attn4_kernel,
                         cudaFuncAttributeMaxDynamicSharedMemorySize, ATTN_SMEM);
    dim3 ga(Ss / 64, NHh, Bb);         // (16, 12, 4)
    attn4_kernel<<<ga, blk, ATTN_SMEM>>>(Qp, Kp, Vp, Att);

    // Output projection + residual (mma.sync tf32)
    gemm_mma<true><<<gq, blk>>>(Att, Wo, bo, query, Oo, MQ, Hh, Hh);

    // LayerNorm into first output region
    ln_kernel<<<MQ, blk>>>(Oo, gamma, beta, out);

    // avg_weights region = constant 1/3
    const int out0 = Bb * Ss * Hh;
    const int navg = out_size - out0;
    int n4 = navg / 4;
    fill_kernel<<<(n4 + 255) / 256, 256>>>(out + out0, n4, 1.0f / 3.0f);
}

// round 9
// speedup vs baseline: 2.9147x; 1.2951x over previous
#include <cuda_runtime.h>
#include <math.h>
#include <stdint.h>

// Problem constants
#define Bb  4
#define Aa  3
#define Ss  1024
#define Hh  768
#define NHh 12
#define HDd 64

// Device scratch (allocation-free rule: __device__ globals)
__device__ float g_Q  [Bb*Ss*Hh];          // Q projection  [B,S,NH,HD]  (tf32, pre-scaled 1/8)
__device__ float g_K  [Bb*Aa*Ss*Hh];       // K projection  [B,A,S,NH,HD] (tf32)
__device__ float g_V  [Bb*Aa*Ss*Hh];       // V projection  [B,A,S,NH,HD] (tf32)
__device__ float g_att[Bb*Ss*Hh];          // attended      [B,S,NH,HD]
__device__ float g_O  [Bb*Ss*Hh];          // pre-LN (proj + residual)

// ===========================================================================
// helpers (arch-portable: compiles for compute_103 without 'a')
// ===========================================================================
__device__ __forceinline__ uint32_t f2tf32(float x) {
    uint32_t r;
    asm("cvt.rna.tf32.f32 %0, %1;" : "=r"(r) : "f"(x));
    return r;
}

__device__ __forceinline__ uint32_t smem_u32(const void* p) {
    uint32_t a;
    asm("{ .reg .u64 t; cvta.to.shared.u64 t, %1; cvt.u32.u64 %0, t; }"
        : "=r"(a) : "l"(p));
    return a;
}

__device__ __forceinline__ void cp_async16(uint32_t dst, const void* src) {
    asm volatile("cp.async.ca.shared.global [%0], [%1], 16;"
                 :: "r"(dst), "l"(src) : "memory");
}
__device__ __forceinline__ void cp_commit() {
    asm volatile("cp.async.commit_group;" ::: "memory");
}
template<int N>
__device__ __forceinline__ void cp_wait() {
    asm volatile("cp.async.wait_group %0;" :: "n"(N) : "memory");
}

// D(16x8,f32) += A(16x8,tf32) * B(8x8,tf32)
__device__ __forceinline__ void mma_tf32(float c[4], const uint32_t a[4],
                                         const uint32_t b[2]) {
    asm volatile(
        "mma.sync.aligned.m16n8k8.row.col.f32.tf32.tf32.f32 "
        "{%0,%1,%2,%3}, {%4,%5,%6,%7}, {%8,%9}, {%0,%1,%2,%3};"
        : "+f"(c[0]), "+f"(c[1]), "+f"(c[2]), "+f"(c[3])
        : "r"(a[0]), "r"(a[1]), "r"(a[2]), "r"(a[3]), "r"(b[0]), "r"(b[1]));
}

// ===========================================================================
// GEMM via mma.sync tf32, register-staged double buffering.
// BM=BN=128, BK=16, 256 threads = 8 warps (4 M x 2 N, warp tile 32x64).
// TFOUT: round output to tf32 (and scale) — producer-side rounding for the
// attention kernel, so attention needs no conversions at all.
// ===========================================================================
template<bool ADD, bool TFOUT>
__global__ __launch_bounds__(256)
void gemm_mma(const float* __restrict__ X, const float* __restrict__ W,
              const float* __restrict__ bias, const float* __restrict__ res,
              float* __restrict__ out, int M, int N, int K, float oscale)
{
    __shared__ float As[2][128 * 20];
    __shared__ float Bs[2][128 * 20];

    const int tid  = threadIdx.x;
    const int lane = tid & 31;
    const int gid  = lane >> 2;
    const int tig  = lane & 3;
    const int wid  = tid >> 5;
    const int wm   = (wid >> 1) * 32;
    const int wn   = (wid & 1) * 64;
    const int m0   = blockIdx.y * 128;
    const int n0   = blockIdx.x * 128;
    const int lr   = tid >> 2;
    const int lc   = (tid & 3) * 4;

    float acc[2][8][4];
#pragma unroll
    for (int mi = 0; mi < 2; mi++)
#pragma unroll
        for (int ni = 0; ni < 8; ni++)
#pragma unroll
            for (int j = 0; j < 4; j++) acc[mi][ni][j] = 0.f;

    float4 xr[2], wr[2];
#pragma unroll
    for (int p = 0; p < 2; p++) {
        xr[p] = *(const float4*)(X + (size_t)(m0 + lr + p * 64) * K + lc);
        wr[p] = *(const float4*)(W + (size_t)(n0 + lr + p * 64) * K + lc);
    }
#pragma unroll
    for (int p = 0; p < 2; p++) {
        uint32_t* ax = (uint32_t*)&As[0][(lr + p * 64) * 20 + lc];
        ax[0] = f2tf32(xr[p].x); ax[1] = f2tf32(xr[p].y);
        ax[2] = f2tf32(xr[p].z); ax[3] = f2tf32(xr[p].w);
        uint32_t* bx = (uint32_t*)&Bs[0][(lr + p * 64) * 20 + lc];
        bx[0] = f2tf32(wr[p].x); bx[1] = f2tf32(wr[p].y);
        bx[2] = f2tf32(wr[p].z); bx[3] = f2tf32(wr[p].w);
    }
    __syncthreads();

    const int NK = K / 16;
    for (int kc = 0; kc < NK; kc++) {
        const int cur = kc & 1;

        if (kc + 1 < NK) {
            const int k0 = (kc + 1) * 16;
#pragma unroll
            for (int p = 0; p < 2; p++) {
                xr[p] = *(const float4*)(X + (size_t)(m0 + lr + p * 64) * K + k0 + lc);
                wr[p] = *(const float4*)(W + (size_t)(n0 + lr + p * 64) * K + k0 + lc);
            }
        }

        const uint32_t* Au = (const uint32_t*)As[cur];
        const uint32_t* Bu = (const uint32_t*)Bs[cur];
#pragma unroll
        for (int ks = 0; ks < 2; ks++) {
            const int kk = ks * 8;
            uint32_t a[2][4], b[8][2];
#pragma unroll
            for (int mi = 0; mi < 2; mi++) {
                int rb = wm + mi * 16;
                a[mi][0] = Au[(rb + gid)     * 20 + kk + tig];
                a[mi][1] = Au[(rb + gid + 8) * 20 + kk + tig];
                a[mi][2] = Au[(rb + gid)     * 20 + kk + tig + 4];
                a[mi][3] = Au[(rb + gid + 8) * 20 + kk + tig + 4];
            }
#pragma unroll
            for (int ni = 0; ni < 8; ni++) {
                int nb = wn + ni * 8 + gid;
                b[ni][0] = Bu[nb * 20 + kk + tig];
                b[ni][1] = Bu[nb * 20 + kk + tig + 4];
            }
#pragma unroll
            for (int mi = 0; mi < 2; mi++)
#pragma unroll
                for (int ni = 0; ni < 8; ni++)
                    mma_tf32(acc[mi][ni], a[mi], b[ni]);
        }

        if (kc + 1 < NK) {
            const int nxt = cur ^ 1;
#pragma unroll
            for (int p = 0; p < 2; p++) {
                uint32_t* ax = (uint32_t*)&As[nxt][(lr + p * 64) * 20 + lc];
                ax[0] = f2tf32(xr[p].x); ax[1] = f2tf32(xr[p].y);
                ax[2] = f2tf32(xr[p].z); ax[3] = f2tf32(xr[p].w);
                uint32_t* bx = (uint32_t*)&Bs[nxt][(lr + p * 64) * 20 + lc];
                bx[0] = f2tf32(wr[p].x); bx[1] = f2tf32(wr[p].y);
                bx[2] = f2tf32(wr[p].z); bx[3] = f2tf32(wr[p].w);
            }
        }
        __syncthreads();
    }

    // Epilogue
#pragma unroll
    for (int mi = 0; mi < 2; mi++) {
        int r0 = m0 + wm + mi * 16 + gid;
        int r1 = r0 + 8;
#pragma unroll
        for (int ni = 0; ni < 8; ni++) {
            int col = n0 + wn + ni * 8 + 2 * tig;
            float b0 = bias[col], b1 = bias[col + 1];
            float2 v0 = make_float2(acc[mi][ni][0] + b0, acc[mi][ni][1] + b1);
            float2 v1 = make_float2(acc[mi][ni][2] + b0, acc[mi][ni][3] + b1);
            if (ADD) {
                float2 ra = *(const float2*)(res + (size_t)r0 * N + col);
                float2 rb = *(const float2*)(res + (size_t)r1 * N + col);
                v0.x += ra.x; v0.y += ra.y;
                v1.x += rb.x; v1.y += rb.y;
            }
            if (TFOUT) {
                v0.x = __uint_as_float(f2tf32(v0.x * oscale));
                v0.y = __uint_as_float(f2tf32(v0.y * oscale));
                v1.x = __uint_as_float(f2tf32(v1.x * oscale));
                v1.y = __uint_as_float(f2tf32(v1.y * oscale));
            }
            *(float2*)(out + (size_t)r0 * N + col) = v0;
            *(float2*)(out + (size_t)r1 * N + col) = v1;
        }
    }
}

// ===========================================================================
// Attention v5 — cp.async double-buffered K/V, zero conversions in-kernel.
//
// Q/K/V arrive pre-rounded to tf32 (Q also pre-scaled by 1/8), so K/V are
// DMA'd gmem->smem with cp.async (no registers, no cvt) and chunk i+1's
// copy overlaps chunk i's compute.
//
// Block: 128 q x (b,h), 512 threads = 16 warps, 1 block/SM.
// Warp (wm=(wid>>1)*16 q-rows, ws=wid&1 key-half): per 32-key chunk it owns
// keys [ws*16, ws*16+16) x 3 adapters (48 k-rows) and the full d=64.
// P stays in registers via the sigma=[0,2,4,6,1,3,5,7] fragment identity.
// smem = 4 * 96*68*4 = 104,448 B (K0,K1,V0,V1).
// ===========================================================================
#define KP 68
#define CHUNK_DW (96 * KP)                 // dwords per buffer
#define ATTN_SMEM (4 * CHUNK_DW * 4)       // 104,448 B

__global__ __launch_bounds__(512, 1)
void attn5_kernel(const float* __restrict__ Q, const float* __restrict__ K,
                  const float* __restrict__ V, float* __restrict__ O)
{
    extern __shared__ float sm[];
    uint32_t* smU = (uint32_t*)sm;
    const uint32_t smBase = smem_u32(sm);

    const int q0  = blockIdx.x * 128;
    const int h   = blockIdx.y;
    const int b   = blockIdx.z;
    const int tid  = threadIdx.x;
    const int lane = tid & 31;
    const int gid  = lane >> 2;
    const int tig  = lane & 3;
    const int wid  = tid >> 5;
    const int wm   = (wid >> 1) * 16;   // q rows: 0..112
    const int ws   = wid & 1;           // key half

    const size_t kvHead = (size_t)h * HDd;

    // cp.async issue for one 32-key chunk into buffer `buf`
    // (3 float4 per thread per array; 16B aligned: KP*4=272=17*16)
    auto issue_chunk = [&](int buf, int s0) {
#pragma unroll
        for (int p = 0; p < 3; p++) {
            int i = p * 512 + tid;
            int r = i >> 4, c4 = (i & 15) * 4;
            int a = r >> 5, s = r & 31;
            size_t gb = ((size_t)((b * Aa + a) * Ss + s0 + s)) * Hh + kvHead + c4;
            uint32_t so = (uint32_t)(r * KP + c4) * 4;
            cp_async16(smBase + buf * (CHUNK_DW * 4) + so, K + gb);
            cp_async16(smBase + (2 + buf) * (CHUNK_DW * 4) + so, V + gb);
        }
        cp_commit();
    };

    // Q fragments in registers for the whole block (pre-scaled, pre-rounded)
    uint32_t qf[8][4];
    {
        const float* Qb = Q + (((size_t)((b * Ss + q0 + wm) * NHh + h)) << 6);
#pragma unroll
        for (int ks = 0; ks < 8; ks++) {
            int c = ks * 8 + tig;
            qf[ks][0] = __float_as_uint(Qb[(size_t)gid * 768 + c]);
            qf[ks][1] = __float_as_uint(Qb[(size_t)(gid + 8) * 768 + c]);
            qf[ks][2] = __float_as_uint(Qb[(size_t)gid * 768 + c + 4]);
            qf[ks][3] = __float_as_uint(Qb[(size_t)(gid + 8) * 768 + c + 4]);
        }
    }

    float co[8][4];
#pragma unroll
    for (int nd = 0; nd < 8; nd++)
#pragma unroll
        for (int j = 0; j < 4; j++) co[nd][j] = 0.f;

    issue_chunk(0, 0);

    for (int ic = 0; ic < 32; ic++) {
        const int cur = ic & 1;

        if (ic + 1 < 32) {
            issue_chunk(cur ^ 1, (ic + 1) * 32);
            cp_wait<1>();       // chunk ic complete (<=1 group pending)
        } else {
            cp_wait<0>();
        }
        __syncthreads();

        const uint32_t* smK = smU + cur * CHUNK_DW;
        const uint32_t* smV = smU + (2 + cur) * CHUNK_DW;

        // ---- scores: cs[ad][ni] = Q(16x64) . K_ad^T (16-key slice) ----
        float cs[3][2][4];
#pragma unroll
        for (int ad = 0; ad < 3; ad++)
#pragma unroll
            for (int ni = 0; ni < 2; ni++)
#pragma unroll
                for (int j = 0; j < 4; j++) cs[ad][ni][j] = 0.f;

#pragma unroll
        for (int ks = 0; ks < 8; ks++) {
            const int kk = ks * 8;
#pragma unroll
            for (int ad = 0; ad < 3; ad++)
#pragma unroll
                for (int ni = 0; ni < 2; ni++) {
                    int krow = ad * 32 + ws * 16 + ni * 8 + gid;
                    uint32_t bb[2];
                    bb[0] = smK[krow * KP + kk + tig];
                    bb[1] = smK[krow * KP + kk + tig + 4];
                    mma_tf32(cs[ad][ni], qf[ks], bb);
                }
        }

        // ---- softmax over adapters in registers (Q pre-scaled by 1/8) ----
#pragma unroll
        for (int ni = 0; ni < 2; ni++)
#pragma unroll
            for (int pos = 0; pos < 4; pos++) {
                float z0 = cs[0][ni][pos];
                float z1 = cs[1][ni][pos];
                float z2 = cs[2][ni][pos];
                float m  = fmaxf(z0, fmaxf(z1, z2));
                float e0 = __expf(z0 - m);
                float e1 = __expf(z1 - m);
                float e2 = __expf(z2 - m);
                float inv = 1.f / (e0 + e1 + e2);
                cs[0][ni][pos] = __uint_as_float(f2tf32(e0 * inv));
                cs[1][ni][pos] = __uint_as_float(f2tf32(e1 * inv));
                cs[2][ni][pos] = __uint_as_float(f2tf32(e2 * inv));
            }

        // ---- PV: co += P(16q x 48n) . V(48n x 64d), P from registers ----
#pragma unroll
        for (int ad = 0; ad < 3; ad++)
#pragma unroll
            for (int ni = 0; ni < 2; ni++) {
                uint32_t A[4];
                A[0] = __float_as_uint(cs[ad][ni][0]);
                A[1] = __float_as_uint(cs[ad][ni][2]);
                A[2] = __float_as_uint(cs[ad][ni][1]);
                A[3] = __float_as_uint(cs[ad][ni][3]);
                const int base = ad * 32 + ws * 16 + ni * 8;
                const uint32_t* v0 = &smV[(base + 2 * tig)     * KP + gid];
                const uint32_t* v1 = &smV[(base + 2 * tig + 1) * KP + gid];
#pragma unroll
                for (int nd = 0; nd < 8; nd++) {
                    uint32_t bb[2] = { v0[nd * 8], v1[nd * 8] };
                    mma_tf32(co[nd], A, bb);
                }
            }

        __syncthreads();   // compute done before next issue overwrites buf cur
    }

    // ---- cross-half reduction (ws=1 partials -> ws=0) and writeout ----
    float* red = sm;            // 128 rows x pitch 66 = 33.8 KB (fits K area)
    const int wmg = wid >> 1;
    if (ws == 1) {
#pragma unroll
        for (int nd = 0; nd < 8; nd++) {
            int c = nd * 8 + 2 * tig;
            *(float2*)&red[(wmg * 16 + gid) * 66 + c] =
                make_float2(co[nd][0], co[nd][1]);
            *(float2*)&red[(wmg * 16 + gid + 8) * 66 + c] =
                make_float2(co[nd][2], co[nd][3]);
        }
    }
    __syncthreads();
    if (ws == 0) {
#pragma unroll
        for (int nd = 0; nd < 8; nd++) {
            int c = nd * 8 + 2 * tig;
            float2 r0 = *(float2*)&red[(wmg * 16 + gid) * 66 + c];
            float2 r1 = *(float2*)&red[(wmg * 16 + gid + 8) * 66 + c];
            int q = q0 + wm + gid;
            *(float2*)(O + (((size_t)((b * Ss + q) * NHh + h)) << 6) + c) =
                make_float2(co[nd][0] + r0.x, co[nd][1] + r0.y);
            *(float2*)(O + (((size_t)((b * Ss + q + 8) * NHh + h)) << 6) + c) =
                make_float2(co[nd][2] + r1.x, co[nd][3] + r1.y);
        }
    }
}

// ---------------------------------------------------------------------------
// Row LayerNorm over H=768
// ---------------------------------------------------------------------------
__global__ __launch_bounds__(256)
void ln_kernel(const float* __restrict__ X, const float* __restrict__ gamma,
               const float* __restrict__ beta, float* __restrict__ out)
{
    __shared__ float red[256];
    const int row = blockIdx.x;
    const int tid = threadIdx.x;
    const float* x = X + (size_t)row * Hh;

    float vals[3];
    float s = 0.f;
#pragma unroll
    for (int i = 0; i < 3; i++) {
        vals[i] = x[tid + i * 256];
        s += vals[i];
    }
    red[tid] = s;
    __syncthreads();
#pragma unroll
    for (int off = 128; off > 0; off >>= 1) {
        if (tid < off) red[tid] += red[tid + off];
        __syncthreads();
    }
    float mean = red[0] * (1.f / Hh);
    __syncthreads();

    float v = 0.f;
#pragma unroll
    for (int i = 0; i < 3; i++) {
        float d = vals[i] - mean;
        v += d * d;
    }
    red[tid] = v;
    __syncthreads();
#pragma unroll
    for (int off = 128; off > 0; off >>= 1) {
        if (tid < off) red[tid] += red[tid + off];
        __syncthreads();
    }
    float inv = rsqrtf(red[0] * (1.f / Hh) + 1e-5f);

#pragma unroll
    for (int i = 0; i < 3; i++) {
        int c = tid + i * 256;
        out[(size_t)row * Hh + c] = (vals[i] - mean) * inv * gamma[c] + beta[c];
    }
}

// avg_weights == 1/3 analytically (softmax over the adapter axis sums to 1)
__global__ void fill_kernel(float* __restrict__ p, int n4, float v)
{
    int i = blockIdx.x * blockDim.x + threadIdx.x;
    if (i < n4) {
        float4 f = make_float4(v, v, v, v);
        *(float4*)(p + (size_t)i * 4) = f;
    }
}

// ---------------------------------------------------------------------------
extern "C" void kernel_launch(void* const* d_in, const int* in_sizes, int n_in,
                              void* d_out, int out_size)
{
    const float* query = (const float*)d_in[0];
    const float* adap  = (const float*)d_in[1];
    const float* Wq = (const float*)d_in[2];  const float* bq = (const float*)d_in[3];
    const float* Wk = (const float*)d_in[4];  const float* bk = (const float*)d_in[5];
    const float* Wv = (const float*)d_in[6];  const float* bv = (const float*)d_in[7];
    const float* Wo = (const float*)d_in[8];  const float* bo = (const float*)d_in[9];
    const float* gamma = (const float*)d_in[10];
    const float* beta  = (const float*)d_in[11];
    float* out = (float*)d_out;

    float *Qp, *Kp, *Vp, *Att, *Oo;
    cudaGetSymbolAddress((void**)&Qp,  g_Q);
    cudaGetSymbolAddress((void**)&Kp,  g_K);
    cudaGetSymbolAddress((void**)&Vp,  g_V);
    cudaGetSymbolAddress((void**)&Att, g_att);
    cudaGetSymbolAddress((void**)&Oo,  g_O);

    const int MQ = Bb * Ss;            // 4096
    const int MKV = Bb * Aa * Ss;      // 12288

    dim3 blk(256);
    dim3 gq(Hh / 128, MQ / 128);       // (6, 32)
    dim3 gkv(Hh / 128, MKV / 128);     // (6, 96)

    // Projections (tf32 mma). Outputs pre-rounded to tf32; Q also pre-scaled
    // by 1/8 (exact power of two — commutes with rounding).
    gemm_mma<false, true><<<gq,  blk>>>(query, Wq, bq, nullptr, Qp, MQ,  Hh, Hh, 0.125f);
    gemm_mma<false, true><<<gkv, blk>>>(adap,  Wk, bk, nullptr, Kp, MKV, Hh, Hh, 1.0f);
    gemm_mma<false, true><<<gkv, blk>>>(adap,  Wv, bv, nullptr, Vp, MKV, Hh, Hh, 1.0f);

    // Attention (cp.async double-buffered, conversion-free)
    cudaFuncSetAttribute(attn5_kernel,
                         cudaFuncAttributeMaxDynamicSharedMemorySize, ATTN_SMEM);
    dim3 ga(Ss / 128, NHh, Bb);        // (8, 12, 4)
    attn5_kernel<<<ga, dim3(512), ATTN_SMEM>>>(Qp, Kp, Vp, Att);

    // Output projection + residual (full fp32 output)
    gemm_mma<true, false><<<gq, blk>>>(Att, Wo, bo, query, Oo, MQ, Hh, Hh, 1.0f);

    // LayerNorm into first output region
    ln_kernel<<<MQ, blk>>>(Oo, gamma, beta, out);

    // avg_weights region = constant 1/3
    const int out0 = Bb * Ss * Hh;
    const int navg = out_size - out0;
    int n4 = navg / 4;
    fill_kernel<<<(n4 + 255) / 256, 256>>>(out + out0, n4, 1.0f / 3.0f);
}

// round 10
// speedup vs baseline: 3.2629x; 1.1195x over previous
#include <cuda_runtime.h>
#include <math.h>
#include <stdint.h>

// Problem constants
#define Bb  4
#define Aa  3
#define Ss  1024
#define Hh  768
#define NHh 12
#define HDd 64

// Device scratch (allocation-free rule: __device__ globals)
__device__ float g_Q  [Bb*Ss*Hh];          // Q projection (tf32 vals, pre-scaled 1/8)
__device__ float g_K  [Bb*Aa*Ss*Hh];       // K projection (tf32 vals)
__device__ float g_V  [Bb*Aa*Ss*Hh];       // V projection (tf32 vals)
__device__ float g_att[Bb*Ss*Hh];          // attended (tf32 vals)
__device__ float g_O  [Bb*Ss*Hh];          // pre-LN (fp32)
// tf32-rounded copies of GEMM inputs (conversion-free cp.async loads)
__device__ float g_Xq [Bb*Ss*Hh];
__device__ float g_Xkv[Bb*Aa*Ss*Hh];
__device__ float g_Wqc[Hh*Hh];
__device__ float g_Wkc[Hh*Hh];
__device__ float g_Wvc[Hh*Hh];
__device__ float g_Woc[Hh*Hh];

// ===========================================================================
// helpers (arch-portable: compiles for compute_103 without 'a')
// ===========================================================================
__device__ __forceinline__ uint32_t f2tf32(float x) {
    uint32_t r;
    asm("cvt.rna.tf32.f32 %0, %1;" : "=r"(r) : "f"(x));
    return r;
}

__device__ __forceinline__ uint32_t smem_u32(const void* p) {
    uint32_t a;
    asm("{ .reg .u64 t; cvta.to.shared.u64 t, %1; cvt.u32.u64 %0, t; }"
        : "=r"(a) : "l"(p));
    return a;
}

__device__ __forceinline__ void cp_async16(uint32_t dst, const void* src) {
    asm volatile("cp.async.ca.shared.global [%0], [%1], 16;"
                 :: "r"(dst), "l"(src) : "memory");
}
__device__ __forceinline__ void cp_commit() {
    asm volatile("cp.async.commit_group;" ::: "memory");
}
template<int N>
__device__ __forceinline__ void cp_wait() {
    asm volatile("cp.async.wait_group %0;" :: "n"(N) : "memory");
}

// D(16x8,f32) += A(16x8,tf32) * B(8x8,tf32)
__device__ __forceinline__ void mma_tf32(float c[4], const uint32_t a[4],
                                         const uint32_t b[2]) {
    asm volatile(
        "mma.sync.aligned.m16n8k8.row.col.f32.tf32.tf32.f32 "
        "{%0,%1,%2,%3}, {%4,%5,%6,%7}, {%8,%9}, {%0,%1,%2,%3};"
        : "+f"(c[0]), "+f"(c[1]), "+f"(c[2]), "+f"(c[3])
        : "r"(a[0]), "r"(a[1]), "r"(a[2]), "r"(a[3]), "r"(b[0]), "r"(b[1]));
}

// Elementwise tf32 rounding pass (producer-side rounding for cp.async GEMMs)
__global__ __launch_bounds__(256)
void cvt_tf32_kernel(const float* __restrict__ in, float* __restrict__ out, int n4)
{
    int i = blockIdx.x * blockDim.x + threadIdx.x;
    if (i < n4) {
        float4 v = ((const float4*)in)[i];
        uint4 o;
        o.x = f2tf32(v.x); o.y = f2tf32(v.y);
        o.z = f2tf32(v.z); o.w = f2tf32(v.w);
        ((uint4*)out)[i] = o;
    }
}

// ===========================================================================
// GEMM via mma.sync tf32 + cp.async (inputs pre-rounded to tf32 in gmem).
// BM=BN=128, BK=32, 256 threads = 8 warps (4 M x 2 N, warp tile 32x64).
// 2-stage cp.async, ONE __syncthreads per chunk: the sync proves both that
// chunk kc is visible and that all warps consumed chunk kc-1, so the issue
// of chunk kc+1 (into kc-1's buffer) placed after the sync is safe and
// overlaps compute(kc).
// Smem pitch 36 floats (144B, 16B-aligned rows; conflict-free fragments).
// smem = 2 stages * 2 arrays * 128*36*4 = 73,728 B -> 2 blocks/SM.
// ===========================================================================
#define GP 36
#define GEMM_STAGE_DW (2 * 128 * GP)              // A+B dwords per stage
#define GEMM_SMEM (2 * GEMM_STAGE_DW * 4)         // 73,728 B

template<bool ADD, bool TFOUT>
__global__ __launch_bounds__(256, 2)
void gemm_cp(const float* __restrict__ X, const float* __restrict__ W,
             const float* __restrict__ bias, const float* __restrict__ res,
             float* __restrict__ out, int M, int N, int K, float oscale)
{
    extern __shared__ float sm[];
    const uint32_t smBase = smem_u32(sm);

    const int tid  = threadIdx.x;
    const int lane = tid & 31;
    const int gid  = lane >> 2;
    const int tig  = lane & 3;
    const int wid  = tid >> 5;
    const int wm   = (wid >> 1) * 32;
    const int wn   = (wid & 1) * 64;
    const int m0   = blockIdx.y * 128;
    const int n0   = blockIdx.x * 128;

    auto issue = [&](int buf, int k0) {
#pragma unroll
        for (int p = 0; p < 4; p++) {
            int idx = p * 256 + tid;
            int r = idx >> 3, c4 = (idx & 7) * 4;
            uint32_t off = (uint32_t)(buf * GEMM_STAGE_DW + r * GP + c4) * 4;
            cp_async16(smBase + off, X + (size_t)(m0 + r) * K + k0 + c4);
            cp_async16(smBase + off + 128 * GP * 4, W + (size_t)(n0 + r) * K + k0 + c4);
        }
        cp_commit();
    };

    float acc[2][8][4];
#pragma unroll
    for (int mi = 0; mi < 2; mi++)
#pragma unroll
        for (int ni = 0; ni < 8; ni++)
#pragma unroll
            for (int j = 0; j < 4; j++) acc[mi][ni][j] = 0.f;

    issue(0, 0);

    const int NK = K / 32;   // 24
    for (int kc = 0; kc < NK; kc++) {
        cp_wait<0>();        // chunk kc complete (issued previous iter)
        __syncthreads();     // visible to all; chunk kc-1 consumed by all
        if (kc + 1 < NK) issue((kc + 1) & 1, (kc + 1) * 32);

        const uint32_t* Au = (const uint32_t*)sm + (kc & 1) * GEMM_STAGE_DW;
        const uint32_t* Bu = Au + 128 * GP;
#pragma unroll
        for (int ks = 0; ks < 4; ks++) {
            const int kk = ks * 8;
            uint32_t a[2][4], b[8][2];
#pragma unroll
            for (int mi = 0; mi < 2; mi++) {
                int rb = wm + mi * 16;
                a[mi][0] = Au[(rb + gid)     * GP + kk + tig];
                a[mi][1] = Au[(rb + gid + 8) * GP + kk + tig];
                a[mi][2] = Au[(rb + gid)     * GP + kk + tig + 4];
                a[mi][3] = Au[(rb + gid + 8) * GP + kk + tig + 4];
            }
#pragma unroll
            for (int ni = 0; ni < 8; ni++) {
                int nb = wn + ni * 8 + gid;
                b[ni][0] = Bu[nb * GP + kk + tig];
                b[ni][1] = Bu[nb * GP + kk + tig + 4];
            }
#pragma unroll
            for (int mi = 0; mi < 2; mi++)
#pragma unroll
                for (int ni = 0; ni < 8; ni++)
                    mma_tf32(acc[mi][ni], a[mi], b[ni]);
        }
    }

    // Epilogue
#pragma unroll
    for (int mi = 0; mi < 2; mi++) {
        int r0 = m0 + wm + mi * 16 + gid;
        int r1 = r0 + 8;
#pragma unroll
        for (int ni = 0; ni < 8; ni++) {
            int col = n0 + wn + ni * 8 + 2 * tig;
            float b0 = bias[col], b1 = bias[col + 1];
            float2 v0 = make_float2(acc[mi][ni][0] + b0, acc[mi][ni][1] + b1);
            float2 v1 = make_float2(acc[mi][ni][2] + b0, acc[mi][ni][3] + b1);
            if (ADD) {
                float2 ra = *(const float2*)(res + (size_t)r0 * N + col);
                float2 rb = *(const float2*)(res + (size_t)r1 * N + col);
                v0.x += ra.x; v0.y += ra.y;
                v1.x += rb.x; v1.y += rb.y;
            }
            if (TFOUT) {
                v0.x = __uint_as_float(f2tf32(v0.x * oscale));
                v0.y = __uint_as_float(f2tf32(v0.y * oscale));
                v1.x = __uint_as_float(f2tf32(v1.x * oscale));
                v1.y = __uint_as_float(f2tf32(v1.y * oscale));
            }
            *(float2*)(out + (size_t)r0 * N + col) = v0;
            *(float2*)(out + (size_t)r1 * N + col) = v1;
        }
    }
}

// ===========================================================================
// Attention v6 — 3-stage cp.async, ONE __syncthreads per chunk.
//
// Block: 128 q x (b,h), 512 threads = 16 warps, 1 block/SM.
// Warp (wm=(wid>>1)*16 q-rows, ws=wid&1 key-half) owns keys
// [ws*16, ws*16+16) x 3 adapters (48 k-rows) and the full d=64 per chunk.
// P stays in registers via the sigma=[0,2,4,6,1,3,5,7] fragment identity.
//
// Pipeline (prefetch distance 2): prologue issues chunks 0,1. Iter ic:
// wait (chunk ic done: <1 pending while issuing, 0 at tail), sync (also
// proves all warps consumed chunk ic-1), issue chunk ic+2 into ic-1's
// buffer, compute chunk ic.
// smem = 6 buffers * 96*68*4 = 156,672 B.
// ===========================================================================
#define KP 68
#define CHUNK_DW (96 * KP)
#define ATTN_SMEM (6 * CHUNK_DW * 4)       // 156,672 B

__global__ __launch_bounds__(512, 1)
void attn6_kernel(const float* __restrict__ Q, const float* __restrict__ K,
                  const float* __restrict__ V, float* __restrict__ O)
{
    extern __shared__ float sm[];
    uint32_t* smU = (uint32_t*)sm;
    const uint32_t smBase = smem_u32(sm);

    const int q0  = blockIdx.x * 128;
    const int h   = blockIdx.y;
    const int b   = blockIdx.z;
    const int tid  = threadIdx.x;
    const int lane = tid & 31;
    const int gid  = lane >> 2;
    const int tig  = lane & 3;
    const int wid  = tid >> 5;
    const int wm   = (wid >> 1) * 16;   // q rows: 0..112
    const int ws   = wid & 1;           // key half

    const size_t kvHead = (size_t)h * HDd;

    auto issue_chunk = [&](int buf, int s0) {
#pragma unroll
        for (int p = 0; p < 3; p++) {
            int i = p * 512 + tid;
            int r = i >> 4, c4 = (i & 15) * 4;
            int a = r >> 5, s = r & 31;
            size_t gb = ((size_t)((b * Aa + a) * Ss + s0 + s)) * Hh + kvHead + c4;
            uint32_t so = (uint32_t)(r * KP + c4) * 4;
            cp_async16(smBase + buf * (CHUNK_DW * 4) + so, K + gb);
            cp_async16(smBase + (3 + buf) * (CHUNK_DW * 4) + so, V + gb);
        }
        cp_commit();
    };

    // Q fragments in registers (pre-scaled by 1/8, pre-rounded tf32)
    uint32_t qf[8][4];
    {
        const float* Qb = Q + (((size_t)((b * Ss + q0 + wm) * NHh + h)) << 6);
#pragma unroll
        for (int ks = 0; ks < 8; ks++) {
            int c = ks * 8 + tig;
            qf[ks][0] = __float_as_uint(Qb[(size_t)gid * 768 + c]);
            qf[ks][1] = __float_as_uint(Qb[(size_t)(gid + 8) * 768 + c]);
            qf[ks][2] = __float_as_uint(Qb[(size_t)gid * 768 + c + 4]);
            qf[ks][3] = __float_as_uint(Qb[(size_t)(gid + 8) * 768 + c + 4]);
        }
    }

    float co[8][4];
#pragma unroll
    for (int nd = 0; nd < 8; nd++)
#pragma unroll
        for (int j = 0; j < 4; j++) co[nd][j] = 0.f;

    issue_chunk(0, 0);
    issue_chunk(1, 32);

    for (int ic = 0; ic < 32; ic++) {
        if (ic < 30) cp_wait<1>();   // chunk ic done; ic+1 may be in flight
        else         cp_wait<0>();   // tail: nothing more issued
        __syncthreads();             // data visible; chunk ic-1 consumed
        if (ic + 2 < 32) {
            int buf = ic + 2;
            buf -= (buf >= 3) ? 3 : 0; buf -= (buf >= 3) ? 3 : 0;
            // (ic+2) % 3 without divide
            issue_chunk((ic + 2) % 3, (ic + 2) * 32);
        }

        int cb = ic % 3;
        const uint32_t* smK = smU + cb * CHUNK_DW;
        const uint32_t* smV = smU + (3 + cb) * CHUNK_DW;

        // ---- scores ----
        float cs[3][2][4];
#pragma unroll
        for (int ad = 0; ad < 3; ad++)
#pragma unroll
            for (int ni = 0; ni < 2; ni++)
#pragma unroll
                for (int j = 0; j < 4; j++) cs[ad][ni][j] = 0.f;

#pragma unroll
        for (int ks = 0; ks < 8; ks++) {
            const int kk = ks * 8;
#pragma unroll
            for (int ad = 0; ad < 3; ad++)
#pragma unroll
                for (int ni = 0; ni < 2; ni++) {
                    int krow = ad * 32 + ws * 16 + ni * 8 + gid;
                    uint32_t bb[2];
                    bb[0] = smK[krow * KP + kk + tig];
                    bb[1] = smK[krow * KP + kk + tig + 4];
                    mma_tf32(cs[ad][ni], qf[ks], bb);
                }
        }

        // ---- softmax over adapters (registers) ----
#pragma unroll
        for (int ni = 0; ni < 2; ni++)
#pragma unroll
            for (int pos = 0; pos < 4; pos++) {
                float z0 = cs[0][ni][pos];
                float z1 = cs[1][ni][pos];
                float z2 = cs[2][ni][pos];
                float m  = fmaxf(z0, fmaxf(z1, z2));
                float e0 = __expf(z0 - m);
                float e1 = __expf(z1 - m);
                float e2 = __expf(z2 - m);
                float inv = 1.f / (e0 + e1 + e2);
                cs[0][ni][pos] = __uint_as_float(f2tf32(e0 * inv));
                cs[1][ni][pos] = __uint_as_float(f2tf32(e1 * inv));
                cs[2][ni][pos] = __uint_as_float(f2tf32(e2 * inv));
            }

        // ---- PV (P from registers via sigma identity) ----
#pragma unroll
        for (int ad = 0; ad < 3; ad++)
#pragma unroll
            for (int ni = 0; ni < 2; ni++) {
                uint32_t A[4];
                A[0] = __float_as_uint(cs[ad][ni][0]);
                A[1] = __float_as_uint(cs[ad][ni][2]);
                A[2] = __float_as_uint(cs[ad][ni][1]);
                A[3] = __float_as_uint(cs[ad][ni][3]);
                const int base = ad * 32 + ws * 16 + ni * 8;
                const uint32_t* v0 = &smV[(base + 2 * tig)     * KP + gid];
                const uint32_t* v1 = &smV[(base + 2 * tig + 1) * KP + gid];
#pragma unroll
                for (int nd = 0; nd < 8; nd++) {
                    uint32_t bb[2] = { v0[nd * 8], v1[nd * 8] };
                    mma_tf32(co[nd], A, bb);
                }
            }
    }

    // ---- cross-half reduction and writeout (tf32-rounded for O-proj) ----
    __syncthreads();
    float* red = sm;
    const int wmg = wid >> 1;
    if (ws == 1) {
#pragma unroll
        for (int nd = 0; nd < 8; nd++) {
            int c = nd * 8 + 2 * tig;
            *(float2*)&red[(wmg * 16 + gid) * 66 + c] =
                make_float2(co[nd][0], co[nd][1]);
            *(float2*)&red[(wmg * 16 + gid + 8) * 66 + c] =
                make_float2(co[nd][2], co[nd][3]);
        }
    }
    __syncthreads();
    if (ws == 0) {
#pragma unroll
        for (int nd = 0; nd < 8; nd++) {
            int c = nd * 8 + 2 * tig;
            float2 r0 = *(float2*)&red[(wmg * 16 + gid) * 66 + c];
            float2 r1 = *(float2*)&red[(wmg * 16 + gid + 8) * 66 + c];
            int q = q0 + wm + gid;
            float2 o0 = make_float2(
                __uint_as_float(f2tf32(co[nd][0] + r0.x)),
                __uint_as_float(f2tf32(co[nd][1] + r0.y)));
            float2 o1 = make_float2(
                __uint_as_float(f2tf32(co[nd][2] + r1.x)),
                __uint_as_float(f2tf32(co[nd][3] + r1.y)));
            *(float2*)(O + (((size_t)((b * Ss + q) * NHh + h)) << 6) + c) = o0;
            *(float2*)(O + (((size_t)((b * Ss + q + 8) * NHh + h)) << 6) + c) = o1;
        }
    }
}

// ---------------------------------------------------------------------------
// Row LayerNorm over H=768
// ---------------------------------------------------------------------------
__global__ __launch_bounds__(256)
void ln_kernel(const float* __restrict__ X, const float* __restrict__ gamma,
               const float* __restrict__ beta, float* __restrict__ out)
{
    __shared__ float red[256];
    const int row = blockIdx.x;
    const int tid = threadIdx.x;
    const float* x = X + (size_t)row * Hh;

    float vals[3];
    float s = 0.f;
#pragma unroll
    for (int i = 0; i < 3; i++) {
        vals[i] = x[tid + i * 256];
        s += vals[i];
    }
    red[tid] = s;
    __syncthreads();
#pragma unroll
    for (int off = 128; off > 0; off >>= 1) {
        if (tid < off) red[tid] += red[tid + off];
        __syncthreads();
    }
    float mean = red[0] * (1.f / Hh);
    __syncthreads();

    float v = 0.f;
#pragma unroll
    for (int i = 0; i < 3; i++) {
        float d = vals[i] - mean;
        v += d * d;
    }
    red[tid] = v;
    __syncthreads();
#pragma unroll
    for (int off = 128; off > 0; off >>= 1) {
        if (tid < off) red[tid] += red[tid + off];
        __syncthreads();
    }
    float inv = rsqrtf(red[0] * (1.f / Hh) + 1e-5f);

#pragma unroll
    for (int i = 0; i < 3; i++) {
        int c = tid + i * 256;
        out[(size_t)row * Hh + c] = (vals[i] - mean) * inv * gamma[c] + beta[c];
    }
}

// avg_weights == 1/3 analytically (softmax over the adapter axis sums to 1)
__global__ void fill_kernel(float* __restrict__ p, int n4, float v)
{
    int i = blockIdx.x * blockDim.x + threadIdx.x;
    if (i < n4) {
        float4 f = make_float4(v, v, v, v);
        *(float4*)(p + (size_t)i * 4) = f;
    }
}

// ---------------------------------------------------------------------------
extern "C" void kernel_launch(void* const* d_in, const int* in_sizes, int n_in,
                              void* d_out, int out_size)
{
    const float* query = (const float*)d_in[0];
    const float* adap  = (const float*)d_in[1];
    const float* Wq = (const float*)d_in[2];  const float* bq = (const float*)d_in[3];
    const float* Wk = (const float*)d_in[4];  const float* bk = (const float*)d_in[5];
    const float* Wv = (const float*)d_in[6];  const float* bv = (const float*)d_in[7];
    const float* Wo = (const float*)d_in[8];  const float* bo = (const float*)d_in[9];
    const float* gamma = (const float*)d_in[10];
    const float* beta  = (const float*)d_in[11];
    float* out = (float*)d_out;

    float *Qp, *Kp, *Vp, *Att, *Oo, *Xq, *Xkv, *Wqc, *Wkc, *Wvc, *Woc;
    cudaGetSymbolAddress((void**)&Qp,  g_Q);
    cudaGetSymbolAddress((void**)&Kp,  g_K);
    cudaGetSymbolAddress((void**)&Vp,  g_V);
    cudaGetSymbolAddress((void**)&Att, g_att);
    cudaGetSymbolAddress((void**)&Oo,  g_O);
    cudaGetSymbolAddress((void**)&Xq,  g_Xq);
    cudaGetSymbolAddress((void**)&Xkv, g_Xkv);
    cudaGetSymbolAddress((void**)&Wqc, g_Wqc);
    cudaGetSymbolAddress((void**)&Wkc, g_Wkc);
    cudaGetSymbolAddress((void**)&Wvc, g_Wvc);
    cudaGetSymbolAddress((void**)&Woc, g_Woc);

    const int MQ = Bb * Ss;            // 4096
    const int MKV = Bb * Aa * Ss;      // 12288

    // Pre-round GEMM inputs to tf32 (producer-side rounding)
    {
        int nq = MQ * Hh / 4, nk = MKV * Hh / 4, nw = Hh * Hh / 4;
        cvt_tf32_kernel<<<(nq + 255) / 256, 256>>>(query, Xq,  nq);
        cvt_tf32_kernel<<<(nk + 255) / 256, 256>>>(adap,  Xkv, nk);
        cvt_tf32_kernel<<<(nw + 255) / 256, 256>>>(Wq, Wqc, nw);
        cvt_tf32_kernel<<<(nw + 255) / 256, 256>>>(Wk, Wkc, nw);
        cvt_tf32_kernel<<<(nw + 255) / 256, 256>>>(Wv, Wvc, nw);
        cvt_tf32_kernel<<<(nw + 255) / 256, 256>>>(Wo, Woc, nw);
    }

    cudaFuncSetAttribute(gemm_cp<false, true>,
                         cudaFuncAttributeMaxDynamicSharedMemorySize, GEMM_SMEM);
    cudaFuncSetAttribute(gemm_cp<true, false>,
                         cudaFuncAttributeMaxDynamicSharedMemorySize, GEMM_SMEM);

    dim3 blk(256);
    dim3 gq(Hh / 128, MQ / 128);       // (6, 32)
    dim3 gkv(Hh / 128, MKV / 128);     // (6, 96)

    // Projections (cp.async tf32 mma). Outputs tf32-rounded; Q pre-scaled 1/8.
    gemm_cp<false, true><<<gq,  blk, GEMM_SMEM>>>(Xq,  Wqc, bq, nullptr, Qp, MQ,  Hh, Hh, 0.125f);
    gemm_cp<false, true><<<gkv, blk, GEMM_SMEM>>>(Xkv, Wkc, bk, nullptr, Kp, MKV, Hh, Hh, 1.0f);
    gemm_cp<false, true><<<gkv, blk, GEMM_SMEM>>>(Xkv, Wvc, bv, nullptr, Vp, MKV, Hh, Hh, 1.0f);

    // Attention (3-stage cp.async, one sync per chunk)
    cudaFuncSetAttribute(attn6_kernel,
                         cudaFuncAttributeMaxDynamicSharedMemorySize, ATTN_SMEM);
    dim3 ga(Ss / 128, NHh, Bb);        // (8, 12, 4)
    attn6_kernel<<<ga, dim3(512), ATTN_SMEM>>>(Qp, Kp, Vp, Att);

    // Output projection + residual (attn output already tf32-rounded)
    gemm_cp<true, false><<<gq, blk, GEMM_SMEM>>>(Att, Woc, bo, query, Oo, MQ, Hh, Hh, 1.0f);

    // LayerNorm into first output region
    ln_kernel<<<MQ, blk>>>(Oo, gamma, beta, out);

    // avg_weights region = constant 1/3
    const int out0 = Bb * Ss * Hh;
    const int navg = out_size - out0;
    int n4 = navg / 4;
    fill_kernel<<<(n4 + 255) / 256, 256>>>(out + out0, n4, 1.0f / 3.0f);
}